// round 8
// baseline (speedup 1.0000x reference)
#include <cuda_runtime.h>
#include <math.h>

#define BB   8
#define FF   48
#define SS   64
#define DD   512
#define NHH  8
#define DHH  64
#define LLAY 4
#define DFFF 2048
#define MMM  64
#define LNEPS 1e-5f

// ---------------- scratch (device globals; allocation-free) ----------------
__device__ float g_q  [BB*DD];            // current-token q (all heads)
__device__ float g_xb [BB*DD];            // layer input x (residual base for self-attn)
__device__ float g_xa [BB*DD];            // x2 after LN2 (ffn input + residual base)
__device__ float g_y  [BB*DD];            // ff2 output (pre-LN3)
__device__ float g_h  [BB*DFFF];          // ffn hidden
__device__ float g_K  [LLAY*BB*FF*DD];    // K cache
__device__ float g_V  [LLAY*BB*FF*DD];    // V cache
__device__ float g_XA [LLAY*BB*FF*DD];    // precomputed cross-attn contribution
__device__ float g_E2 [BB*FF*DD];         // precomputed emb part: sel@W2 + se_b + style + PE
__device__ float g_qh [BB*FF*DD];
__device__ float g_kh [BB*SS*DD];
__device__ float g_vh [BB*SS*DD];
__device__ float g_tmp[BB*FF*DD];

// ---------------- helpers ----------------
__device__ __forceinline__ float warp_sum(float v){
#pragma unroll
    for (int o = 16; o; o >>= 1) v += __shfl_xor_sync(0xffffffffu, v, o);
    return v;
}

// block of 512 threads; scr must be float[33] shared
__device__ __forceinline__ float block_sum512(float v, float* scr){
    int lane = threadIdx.x & 31, warp = threadIdx.x >> 5;
    v = warp_sum(v);
    if (lane == 0) scr[warp] = v;
    __syncthreads();
    if (warp == 0){
        float r = (lane < 16) ? scr[lane] : 0.f;
        r = warp_sum(r);
        if (lane == 0) scr[32] = r;
    }
    __syncthreads();
    float r = scr[32];
    __syncthreads();
    return r;
}

// ---------------- generic row-batched matvec: out[r,n] = X[r,:]·W[n,:] + b[n] ----
// grid = (N/8, R/8), block 256 (8 warps; warp owns one n over 8 rows)
__global__ void gemm_rows_kernel(float* __restrict__ out, const float* __restrict__ X,
                                 const float* __restrict__ W, const float* __restrict__ bias,
                                 int N, int K){
    int warp = threadIdx.x >> 5, lane = threadIdx.x & 31;
    int n  = blockIdx.x * 8 + warp;
    int r0 = blockIdx.y * 8;
    const float* w = W + (size_t)n * K;
    const float* x = X + (size_t)r0 * K;
    float acc[8] = {0.f,0.f,0.f,0.f,0.f,0.f,0.f,0.f};
    for (int k = lane; k < K; k += 32){
        float wv = w[k];
#pragma unroll
        for (int b = 0; b < 8; b++) acc[b] += wv * x[(size_t)b*K + k];
    }
#pragma unroll
    for (int o = 16; o; o >>= 1){
#pragma unroll
        for (int b = 0; b < 8; b++) acc[b] += __shfl_xor_sync(0xffffffffu, acc[b], o);
    }
    float bv = bias[n];
#pragma unroll
    for (int b = 0; b < 8; b++)
        if (lane == b) out[(size_t)(r0 + b) * N + n] = acc[b] + bv;
}

// ---------------- `sel` cross-attn (nh=1, softmax over S=64, no mask) -----------
// grid = B*F (one query row), block 256
__global__ void ca_attn_kernel(const float* __restrict__ qh, const float* __restrict__ kh,
                               const float* __restrict__ vh, float* __restrict__ o){
    int r = blockIdx.x;                  // b*FF + f
    int b = r / FF;
    __shared__ float s_q[DD];
    __shared__ float s_p[SS];
    int tid = threadIdx.x, warp = tid >> 5, lane = tid & 31;
    for (int d = tid; d < DD; d += 256) s_q[d] = qh[(size_t)r*DD + d];
    __syncthreads();
    for (int s = warp; s < SS; s += 8){
        const float* kr = kh + (size_t)(b*SS + s)*DD;
        float a = 0.f;
        for (int k = lane; k < DD; k += 32) a += s_q[k] * kr[k];
        a = warp_sum(a);
        if (lane == 0) s_p[s] = a * 0.04419417382415922f;   // 1/sqrt(512)
    }
    __syncthreads();
    if (warp == 0){
        float v0 = s_p[lane], v1 = s_p[lane + 32];
        float m = fmaxf(v0, v1);
#pragma unroll
        for (int o2 = 16; o2; o2 >>= 1) m = fmaxf(m, __shfl_xor_sync(0xffffffffu, m, o2));
        float e0 = expf(v0 - m), e1 = expf(v1 - m);
        float sm = warp_sum(e0 + e1);
        float inv = 1.f / sm;
        s_p[lane] = e0 * inv; s_p[lane + 32] = e1 * inv;
    }
    __syncthreads();
    for (int d = tid; d < DD; d += 256){
        float a = 0.f;
#pragma unroll 8
        for (int s = 0; s < SS; s++) a += s_p[s] * vh[(size_t)(b*SS + s)*DD + d];
        o[(size_t)r*DD + d] = a;
    }
}

// ---------------- E2 precompute: E2[b,p,n] = sel[b,idx(p)]·W2[n,:] + se_b + style + PE
// grid = (64, 48), block 256
__global__ void e2_kernel(const float* __restrict__ sel, const float* __restrict__ se_w,
                          const float* __restrict__ se_b, const float* __restrict__ style){
    int warp = threadIdx.x >> 5, lane = threadIdx.x & 31;
    int n  = blockIdx.x * 8 + warp;      // 0..511
    int r0 = blockIdx.y * 8;             // rows r = b*48 + p (48%8==0: same b per block)
    int b  = r0 / FF;
    const float* w = se_w + (size_t)n * 1024 + 512;   // W2 row n
    const float* xr[8];
#pragma unroll
    for (int q = 0; q < 8; q++){
        int p  = (r0 + q) % FF;
        int ip = p ? (p - 1) : 0;
        xr[q] = sel + ((size_t)b*FF + ip)*DD;
    }
    float acc[8] = {0.f,0.f,0.f,0.f,0.f,0.f,0.f,0.f};
    for (int k = lane; k < DD; k += 32){
        float wv = w[k];
#pragma unroll
        for (int q = 0; q < 8; q++) acc[q] += wv * xr[q][k];
    }
#pragma unroll
    for (int o = 16; o; o >>= 1){
#pragma unroll
        for (int q = 0; q < 8; q++) acc[q] += __shfl_xor_sync(0xffffffffu, acc[q], o);
    }
#pragma unroll
    for (int q = 0; q < 8; q++){
        if (lane == q){
            int p = (r0 + q) % FF;
            float pos = (float)(p % 30);
            const float LF = 9.210340371976184f / 512.f;     // ln(10000)/512
            float pe;
            if (n & 1) pe = cosf(pos * expf(-(float)(n - 1) * LF));
            else       pe = sinf(pos * expf(-(float)n       * LF));
            g_E2[((size_t)r0 + q)*DD + n] = acc[q] + se_b[n] + style[b*DD + n] + pe;
        }
    }
}

// ---------------- init: feat0 = init_state@mm_w^T+mm_b; x0 = feat0@W1^T + E2[b,0]
// grid 8 (batch), block 512
__global__ void init_x0_kernel(const float* __restrict__ init_state, const float* __restrict__ mm_w,
                               const float* __restrict__ mm_b, const float* __restrict__ se_w){
    int b = blockIdx.x, d = threadIdx.x;
    __shared__ float s_feat[DD];
    float a = mm_b[d];
    const float* mw = mm_w + (size_t)d * MMM;
    const float* is = init_state + b * MMM;
#pragma unroll
    for (int k = 0; k < MMM; k++) a += is[k] * mw[k];
    s_feat[d] = a;
    __syncthreads();
    const float* w1 = se_w + (size_t)d * 1024;   // W1 row d
    float a0=0.f,a1=0.f,a2=0.f,a3=0.f;
    for (int k = 0; k < DD; k += 4){
        a0 += s_feat[k]   * w1[k];
        a1 += s_feat[k+1] * w1[k+1];
        a2 += s_feat[k+2] * w1[k+2];
        a3 += s_feat[k+3] * w1[k+3];
    }
    g_xb[b*DD + d] = a0+a1+a2+a3 + g_E2[((size_t)b*FF + 0)*DD + d];
}

// ---------------- step: QKV projection (optionally fused with previous layer's LN3)
// grid = 192, block 256 (8 warps; warp owns one of 1536 outputs over 8 batches)
__global__ void qkv_kernel(const float* __restrict__ W, const float* __restrict__ bias,
                           const float* __restrict__ lng, const float* __restrict__ lnb,
                           int fuse, int l, int t){
    __shared__ float s_x[BB][DD];        // 16KB
    int tid = threadIdx.x, warp = tid >> 5, lane = tid & 31;
    if (!fuse){
        for (int j = tid; j < BB*DD; j += 256) s_x[j >> 9][j & 511] = g_xb[j];
    } else {
        int b = warp;                    // 8 warps, one batch row each: LN3(x2 + ffn)
        float sum = 0.f;
        for (int k = lane; k < DD; k += 32){
            float v = g_xa[b*DD + k] + g_y[b*DD + k];
            s_x[b][k] = v; sum += v;
        }
        sum = warp_sum(sum);
        float mu = sum * (1.f / DD);
        float vs = 0.f;
        for (int k = lane; k < DD; k += 32){ float dv = s_x[b][k] - mu; vs += dv*dv; }
        vs = warp_sum(vs);
        float rstd = rsqrtf(vs * (1.f / DD) + LNEPS);
        for (int k = lane; k < DD; k += 32)
            s_x[b][k] = (s_x[b][k] - mu) * rstd * lng[k] + lnb[k];
    }
    __syncthreads();
    if (fuse && blockIdx.x == 0){        // materialize layer input for residual use
        for (int j = tid; j < BB*DD; j += 256) g_xb[j] = s_x[j >> 9][j & 511];
    }
    int n = blockIdx.x * 8 + warp;       // 0..1535
    const float* w = W + (size_t)n * DD;
    float acc[8] = {0.f,0.f,0.f,0.f,0.f,0.f,0.f,0.f};
    for (int k = lane; k < DD; k += 32){
        float wv = w[k];
#pragma unroll
        for (int b = 0; b < 8; b++) acc[b] += wv * s_x[b][k];
    }
#pragma unroll
    for (int o = 16; o; o >>= 1){
#pragma unroll
        for (int b = 0; b < 8; b++) acc[b] += __shfl_xor_sync(0xffffffffu, acc[b], o);
    }
    float bv = bias[n];
#pragma unroll
    for (int b = 0; b < 8; b++){
        if (lane == b){
            float v = acc[b] + bv;
            if (n < DD)        g_q[b*DD + n] = v;
            else if (n < 2*DD) g_K[(((size_t)l*BB + b)*FF + t)*DD + (n - DD)]   = v;
            else               g_V[(((size_t)l*BB + b)*FF + t)*DD + (n - 2*DD)] = v;
        }
    }
}

// ---------------- step: self-attn + out-proj + LN1 + XA + LN2 -------------------
// grid = 8 (batch), block = 512
__global__ void attn_out_ln_kernel(const float* __restrict__ Wo, const float* __restrict__ bo,
        const float* __restrict__ lng1, const float* __restrict__ lnb1,
        const float* __restrict__ lng2, const float* __restrict__ lnb2,
        int l, int t){
    int b = blockIdx.x;
    __shared__ float s_q[DD], s_xr[DD], s_attn[DD], s_r[DD];
    __shared__ float s_p[NHH][FF];
    __shared__ float scr[33];
    int tid = threadIdx.x, warp = tid >> 5, lane = tid & 31;
    s_q [tid] = g_q [b*DD + tid];
    s_xr[tid] = g_xb[b*DD + tid];
    __syncthreads();
    if (warp < NHH){
        int h = warp;
        const float* qv = s_q + h*DHH;
        const float* Kb = g_K + (((size_t)l*BB + b)*FF)*DD + h*DHH;
        const float* Vb = g_V + (((size_t)l*BB + b)*FF)*DD + h*DHH;
        float slope = exp2f(-(float)(h + 1));
        int j0 = lane, j1 = lane + 32;
        float sc0 = -1e30f, sc1 = -1e30f;
        if (j0 <= t){
            const float* kr = Kb + (size_t)j0*DD;
            float a = 0.f;
#pragma unroll
            for (int d = 0; d < DHH; d++) a += qv[d]*kr[d];
            sc0 = a*0.125f - slope * (float)((t - j0)/30);
        }
        if (j1 <= t){
            const float* kr = Kb + (size_t)j1*DD;
            float a = 0.f;
#pragma unroll
            for (int d = 0; d < DHH; d++) a += qv[d]*kr[d];
            sc1 = a*0.125f - slope * (float)((t - j1)/30);
        }
        float m = fmaxf(sc0, sc1);
#pragma unroll
        for (int o = 16; o; o >>= 1) m = fmaxf(m, __shfl_xor_sync(0xffffffffu, m, o));
        float e0 = (j0 <= t) ? expf(sc0 - m) : 0.f;
        float e1 = (j1 <= t) ? expf(sc1 - m) : 0.f;
        float sm = warp_sum(e0 + e1);
        float inv = 1.f / sm;
        if (j0 < FF) s_p[h][j0] = e0 * inv;
        if (j1 < FF) s_p[h][j1] = e1 * inv;
        __syncwarp();
        for (int d = lane; d < DHH; d += 32){
            float a = 0.f;
            for (int j = 0; j <= t; j++) a += s_p[h][j] * Vb[(size_t)j*DD + d];
            s_attn[h*DHH + d] = a;
        }
    }
    __syncthreads();
    // out projection + bias + residual
    for (int dd = 0; dd < 32; dd++){
        int d = warp*32 + dd;
        const float* w = Wo + (size_t)d*DD;
        float a = 0.f;
        for (int k = lane; k < DD; k += 32) a += s_attn[k]*w[k];
        a = warp_sum(a);
        if (lane == 0) s_r[d] = a + bo[d] + s_xr[d];
    }
    __syncthreads();
    // LN1
    float v   = s_r[tid];
    float mu  = block_sum512(v, scr) * (1.f / DD);
    float dv  = v - mu;
    float var = block_sum512(dv*dv, scr) * (1.f / DD);
    float x1  = dv * rsqrtf(var + LNEPS) * lng1[tid] + lnb1[tid];
    // + precomputed cross-attn, LN2
    float r2  = x1 + g_XA[(((size_t)l*BB + b)*FF + t)*DD + tid];
    mu  = block_sum512(r2, scr) * (1.f / DD);
    dv  = r2 - mu;
    var = block_sum512(dv*dv, scr) * (1.f / DD);
    g_xa[b*DD + tid] = dv * rsqrtf(var + LNEPS) * lng2[tid] + lnb2[tid];
}

// ---------------- step: ff1 (relu) -----------------------------------------------
// grid 256, block 256 (warp-per-output over 8 batches)
__global__ void ff1_kernel(const float* __restrict__ W, const float* __restrict__ bias){
    __shared__ float s_x[BB][DD];
    int tid = threadIdx.x, warp = tid >> 5, lane = tid & 31;
    for (int j = tid; j < BB*DD; j += 256) s_x[j >> 9][j & 511] = g_xa[j];
    __syncthreads();
    int n = blockIdx.x * 8 + warp;       // 0..2047
    const float* w = W + (size_t)n * DD;
    float acc[8] = {0.f,0.f,0.f,0.f,0.f,0.f,0.f,0.f};
    for (int k = lane; k < DD; k += 32){
        float wv = w[k];
#pragma unroll
        for (int b = 0; b < 8; b++) acc[b] += wv * s_x[b][k];
    }
#pragma unroll
    for (int o = 16; o; o >>= 1){
#pragma unroll
        for (int b = 0; b < 8; b++) acc[b] += __shfl_xor_sync(0xffffffffu, acc[b], o);
    }
    float bv = bias[n];
#pragma unroll
    for (int b = 0; b < 8; b++)
        if (lane == b) g_h[b*DFFF + n] = fmaxf(acc[b] + bv, 0.f);
}

// ---------------- step: ff2 ------------------------------------------------------
// grid 64, block 256 (warp-per-output over 8 batches, K=2048)
__global__ void ff2_kernel(const float* __restrict__ W, const float* __restrict__ bias){
    int warp = threadIdx.x >> 5, lane = threadIdx.x & 31;
    int n = blockIdx.x * 8 + warp;       // 0..511
    const float* w = W + (size_t)n * DFFF;
    float acc[8] = {0.f,0.f,0.f,0.f,0.f,0.f,0.f,0.f};
    for (int k = lane; k < DFFF; k += 32){
        float wv = w[k];
#pragma unroll
        for (int b = 0; b < 8; b++) acc[b] += wv * g_h[b*DFFF + k];
    }
#pragma unroll
    for (int o = 16; o; o >>= 1){
#pragma unroll
        for (int b = 0; b < 8; b++) acc[b] += __shfl_xor_sync(0xffffffffu, acc[b], o);
    }
    float bv = bias[n];
#pragma unroll
    for (int b = 0; b < 8; b++)
        if (lane == b) g_y[b*DD + n] = acc[b] + bv;
}

// ---------------- step: final LN3 + head + next embedding -----------------------
// grid 8 (batch), block 512
__global__ void head_kernel(const float* __restrict__ lng3, const float* __restrict__ lnb3,
                            const float* __restrict__ mmr_w, const float* __restrict__ mmr_b,
                            const float* __restrict__ mm_w,  const float* __restrict__ mm_b,
                            const float* __restrict__ se_w,  float* __restrict__ dec_out, int t){
    int b = blockIdx.x, tid = threadIdx.x, warp = tid >> 5, lane = tid & 31;
    __shared__ float s_x[DD], s_out[MMM], s_feat[DD], scr[33];
    float v   = g_xa[b*DD + tid] + g_y[b*DD + tid];
    float mu  = block_sum512(v, scr) * (1.f / DD);
    float dv  = v - mu;
    float var = block_sum512(dv*dv, scr) * (1.f / DD);
    s_x[tid]  = dv * rsqrtf(var + LNEPS) * lng3[tid] + lnb3[tid];
    __syncthreads();
#pragma unroll
    for (int q = 0; q < 4; q++){
        int j = warp*4 + q;              // 0..63
        const float* w = mmr_w + (size_t)j*DD;
        float a = 0.f;
        for (int k = lane; k < DD; k += 32) a += s_x[k]*w[k];
        a = warp_sum(a);
        if (lane == 0){
            a += mmr_b[j];
            s_out[j] = a;
            dec_out[((size_t)b*FF + t)*MMM + j] = a;
        }
    }
    __syncthreads();
    if (t < FF - 1){
        float a = mm_b[tid];
        const float* mw = mm_w + (size_t)tid * MMM;
#pragma unroll
        for (int k = 0; k < MMM; k++) a += s_out[k]*mw[k];
        s_feat[tid] = a;
        __syncthreads();
        const float* w1 = se_w + (size_t)tid * 1024;
        float a0=0.f,a1=0.f,a2=0.f,a3=0.f;
        for (int k = 0; k < DD; k += 4){
            a0 += s_feat[k]   * w1[k];
            a1 += s_feat[k+1] * w1[k+1];
            a2 += s_feat[k+2] * w1[k+2];
            a3 += s_feat[k+3] * w1[k+3];
        }
        g_xb[b*DD + tid] = a0+a1+a2+a3 + g_E2[((size_t)b*FF + t + 1)*DD + tid];
    }
}

// ---------------- launch ---------------------------------------------------------
extern "C" void kernel_launch(void* const* d_in, const int* in_sizes, int n_in,
                              void* d_out, int out_size){
    const float* content       = (const float*)d_in[0];
    const float* style_code    = (const float*)d_in[1];
    const float* style_hiddens = (const float*)d_in[2];
    const float* init_state    = (const float*)d_in[3];
    const float* ca_in_w  = (const float*)d_in[4];
    const float* ca_in_b  = (const float*)d_in[5];
    const float* ca_out_w = (const float*)d_in[6];
    const float* ca_out_b = (const float*)d_in[7];
    const float* se_w     = (const float*)d_in[8];
    const float* se_b     = (const float*)d_in[9];
    const float* mm_w     = (const float*)d_in[10];
    const float* mm_b     = (const float*)d_in[11];
    const float* mmr_w    = (const float*)d_in[12];
    const float* mmr_b    = (const float*)d_in[13];
    const float* sa_in_w  = (const float*)d_in[14];
    const float* sa_in_b  = (const float*)d_in[15];
    const float* sa_out_w = (const float*)d_in[16];
    const float* sa_out_b = (const float*)d_in[17];
    const float* xa_in_w  = (const float*)d_in[18];
    const float* xa_in_b  = (const float*)d_in[19];
    const float* xa_out_w = (const float*)d_in[20];
    const float* xa_out_b = (const float*)d_in[21];
    const float* ff1_w    = (const float*)d_in[22];
    const float* ff1_b    = (const float*)d_in[23];
    const float* ff2_w    = (const float*)d_in[24];
    const float* ff2_b    = (const float*)d_in[25];
    const float* ln_g     = (const float*)d_in[26];
    const float* ln_b     = (const float*)d_in[27];

    float* dec_out = (float*)d_out;                      // (B,48,64)
    float* sel     = (float*)d_out + BB*FF*MMM;          // (B,48,512)

    float *A_qh, *A_kh, *A_vh, *A_tmp, *A_XA;
    cudaGetSymbolAddress((void**)&A_qh,  g_qh);
    cudaGetSymbolAddress((void**)&A_kh,  g_kh);
    cudaGetSymbolAddress((void**)&A_vh,  g_vh);
    cudaGetSymbolAddress((void**)&A_tmp, g_tmp);
    cudaGetSymbolAddress((void**)&A_XA,  g_XA);

    dim3 blk(256);

    // ---- sel = CA(content, style_hiddens) (nh=1) ----
    gemm_rows_kernel<<<dim3(64,48), blk>>>(A_qh, content,       ca_in_w,           ca_in_b,        DD, DD);
    gemm_rows_kernel<<<dim3(64,64), blk>>>(A_kh, style_hiddens, ca_in_w +   DD*DD, ca_in_b +   DD, DD, DD);
    gemm_rows_kernel<<<dim3(64,64), blk>>>(A_vh, style_hiddens, ca_in_w + 2*DD*DD, ca_in_b + 2*DD, DD, DD);
    ca_attn_kernel<<<BB*FF, 256>>>(A_qh, A_kh, A_vh, A_tmp);
    gemm_rows_kernel<<<dim3(64,48), blk>>>(sel, A_tmp, ca_out_w, ca_out_b, DD, DD);

    // ---- XA[l] = (content @ Wv_l^T + bv_l) @ Wo_l^T + bo_l (diagonal-mask collapse) ----
    for (int l = 0; l < LLAY; l++){
        const float* wv = xa_in_w + (size_t)l*3*DD*DD + 2*DD*DD;
        const float* bv = xa_in_b + (size_t)l*3*DD    + 2*DD;
        gemm_rows_kernel<<<dim3(64,48), blk>>>(A_qh, content, wv, bv, DD, DD);
        gemm_rows_kernel<<<dim3(64,48), blk>>>(A_XA + (size_t)l*BB*FF*DD, A_qh,
                                               xa_out_w + (size_t)l*DD*DD,
                                               xa_out_b + (size_t)l*DD, DD, DD);
    }

    // ---- E2 table + x0 for t=0 ----
    e2_kernel<<<dim3(64,48), 256>>>(sel, se_w, se_b, style_code);
    init_x0_kernel<<<BB, 512>>>(init_state, mm_w, mm_b, se_w);

    // ---- autoregressive decode: 48 steps ----
    for (int t = 0; t < FF; t++){
        for (int l = 0; l < LLAY; l++){
            const float* lng3p = (l > 0) ? (ln_g + ((size_t)(l-1)*3 + 2)*DD) : (const float*)0;
            const float* lnb3p = (l > 0) ? (ln_b + ((size_t)(l-1)*3 + 2)*DD) : (const float*)0;
            qkv_kernel<<<192, 256>>>(sa_in_w + (size_t)l*3*DD*DD, sa_in_b + (size_t)l*3*DD,
                                     lng3p, lnb3p, (l > 0) ? 1 : 0, l, t);
            attn_out_ln_kernel<<<BB, 512>>>(sa_out_w + (size_t)l*DD*DD, sa_out_b + (size_t)l*DD,
                                            ln_g + ((size_t)l*3 + 0)*DD, ln_b + ((size_t)l*3 + 0)*DD,
                                            ln_g + ((size_t)l*3 + 1)*DD, ln_b + ((size_t)l*3 + 1)*DD,
                                            l, t);
            ff1_kernel<<<256, 256>>>(ff1_w + (size_t)l*DFFF*DD, ff1_b + (size_t)l*DFFF);
            ff2_kernel<<< 64, 256>>>(ff2_w + (size_t)l*DD*DFFF, ff2_b + (size_t)l*DD);
        }
        head_kernel<<<BB, 512>>>(ln_g + (3*3 + 2)*DD, ln_b + (3*3 + 2)*DD,
                                 mmr_w, mmr_b, mm_w, mm_b, se_w, dec_out, t);
    }
}

// round 9
// speedup vs baseline: 2.4157x; 2.4157x over previous
#include <cuda_runtime.h>
#include <math.h>

#define BB   8
#define FF   48
#define SS   64
#define DD   512
#define NHH  8
#define DHH  64
#define LLAY 4
#define DFFF 2048
#define MMM  64
#define LNEPS 1e-5f
#define GRID 128          // persistent blocks (<= SM count -> all co-resident)
#define NWARP (GRID*8)    // 1024 warps

// ---------------- scratch (device globals; allocation-free) ----------------
__device__ float g_q   [BB*DD];
__device__ float g_xb  [BB*DD];           // layer input x (residual base)
__device__ float g_xa  [BB*DD];           // x2 after LN2
__device__ float g_y   [BB*DD];           // ff2 output
__device__ float g_h   [BB*DFFF];
__device__ float g_r   [BB*DD];           // out-proj + residual (pre-LN1)
__device__ float g_attn[BB*DD];
__device__ float g_out [BB*MMM];
__device__ float g_K   [LLAY*BB*FF*DD];
__device__ float g_V   [LLAY*BB*FF*DD];
__device__ float g_XA  [LLAY*BB*FF*DD];   // precomputed cross-attn contribution
__device__ float g_E2  [BB*FF*DD];        // sel@W2 + se_b + style + PE
__device__ float g_CW  [DD*MMM];          // W1 @ mm_w  (512 x 64)
__device__ float g_cb  [DD];              // W1 @ mm_b
__device__ float g_qh  [BB*FF*DD];
__device__ float g_kh  [BB*SS*DD];
__device__ float g_vh  [BB*SS*DD];
__device__ float g_tmp [BB*FF*DD];

__device__ unsigned g_cnt;                // barrier arrivals (self-resetting)
__device__ unsigned g_gen;                // barrier generation

// ---------------- helpers ----------------
__device__ __forceinline__ float warp_sum(float v){
#pragma unroll
    for (int o = 16; o; o >>= 1) v += __shfl_xor_sync(0xffffffffu, v, o);
    return v;
}

__device__ __forceinline__ void grid_sync(){
    __syncthreads();
    if (threadIdx.x == 0){
        unsigned g;
        asm volatile("ld.acquire.gpu.u32 %0, [%1];" : "=r"(g) : "l"(&g_gen) : "memory");
        __threadfence();
        unsigned prev = atomicAdd(&g_cnt, 1u);
        if (prev == GRID - 1u){
            g_cnt = 0u;
            asm volatile("st.release.gpu.u32 [%0], %1;" :: "l"(&g_gen), "r"(g + 1u) : "memory");
        } else {
            unsigned cur;
            do {
                __nanosleep(64);
                asm volatile("ld.acquire.gpu.u32 %0, [%1];" : "=r"(cur) : "l"(&g_gen) : "memory");
            } while (cur == g);
        }
    }
    __syncthreads();
}

// ================= one-time precompute kernels =================

// out[r,n] = X[r,:]·W[n,:] + b[n];  grid=(N/8, R/8), block 256
__global__ void gemm_rows_kernel(float* __restrict__ out, const float* __restrict__ X,
                                 const float* __restrict__ W, const float* __restrict__ bias,
                                 int N, int K){
    int warp = threadIdx.x >> 5, lane = threadIdx.x & 31;
    int n  = blockIdx.x * 8 + warp;
    int r0 = blockIdx.y * 8;
    const float* w = W + (size_t)n * K;
    const float* x = X + (size_t)r0 * K;
    float acc[8] = {0.f,0.f,0.f,0.f,0.f,0.f,0.f,0.f};
    for (int k = lane; k < K; k += 32){
        float wv = w[k];
#pragma unroll
        for (int b = 0; b < 8; b++) acc[b] += wv * x[(size_t)b*K + k];
    }
#pragma unroll
    for (int o = 16; o; o >>= 1){
#pragma unroll
        for (int b = 0; b < 8; b++) acc[b] += __shfl_xor_sync(0xffffffffu, acc[b], o);
    }
    float bv = bias[n];
#pragma unroll
    for (int b = 0; b < 8; b++)
        if (lane == b) out[(size_t)(r0 + b) * N + n] = acc[b] + bv;
}

// sel cross-attn (nh=1, softmax over S=64); grid = B*F, block 256
__global__ void ca_attn_kernel(const float* __restrict__ qh, const float* __restrict__ kh,
                               const float* __restrict__ vh, float* __restrict__ o){
    int r = blockIdx.x;
    int b = r / FF;
    __shared__ float s_q[DD];
    __shared__ float s_p[SS];
    int tid = threadIdx.x, warp = tid >> 5, lane = tid & 31;
    for (int d = tid; d < DD; d += 256) s_q[d] = qh[(size_t)r*DD + d];
    __syncthreads();
    for (int s = warp; s < SS; s += 8){
        const float* kr = kh + (size_t)(b*SS + s)*DD;
        float a = 0.f;
        for (int k = lane; k < DD; k += 32) a += s_q[k] * kr[k];
        a = warp_sum(a);
        if (lane == 0) s_p[s] = a * 0.04419417382415922f;
    }
    __syncthreads();
    if (warp == 0){
        float v0 = s_p[lane], v1 = s_p[lane + 32];
        float m = fmaxf(v0, v1);
#pragma unroll
        for (int o2 = 16; o2; o2 >>= 1) m = fmaxf(m, __shfl_xor_sync(0xffffffffu, m, o2));
        float e0 = expf(v0 - m), e1 = expf(v1 - m);
        float sm = warp_sum(e0 + e1);
        float inv = 1.f / sm;
        s_p[lane] = e0 * inv; s_p[lane + 32] = e1 * inv;
    }
    __syncthreads();
    for (int d = tid; d < DD; d += 256){
        float a = 0.f;
#pragma unroll 8
        for (int s = 0; s < SS; s++) a += s_p[s] * vh[(size_t)(b*SS + s)*DD + d];
        o[(size_t)r*DD + d] = a;
    }
}

// E2[b,p,n] = sel[b,p?p-1:0]·W2[n,:] + se_b[n] + style[b,n] + PE[p,n]
__global__ void e2_kernel(const float* __restrict__ sel, const float* __restrict__ se_w,
                          const float* __restrict__ se_b, const float* __restrict__ style){
    int warp = threadIdx.x >> 5, lane = threadIdx.x & 31;
    int n  = blockIdx.x * 8 + warp;
    int r0 = blockIdx.y * 8;
    int b  = r0 / FF;
    const float* w = se_w + (size_t)n * 1024 + 512;
    const float* xr[8];
#pragma unroll
    for (int q = 0; q < 8; q++){
        int p  = (r0 + q) % FF;
        int ip = p ? (p - 1) : 0;
        xr[q] = sel + ((size_t)b*FF + ip)*DD;
    }
    float acc[8] = {0.f,0.f,0.f,0.f,0.f,0.f,0.f,0.f};
    for (int k = lane; k < DD; k += 32){
        float wv = w[k];
#pragma unroll
        for (int q = 0; q < 8; q++) acc[q] += wv * xr[q][k];
    }
#pragma unroll
    for (int o = 16; o; o >>= 1){
#pragma unroll
        for (int q = 0; q < 8; q++) acc[q] += __shfl_xor_sync(0xffffffffu, acc[q], o);
    }
#pragma unroll
    for (int q = 0; q < 8; q++){
        if (lane == q){
            int p = (r0 + q) % FF;
            float pos = (float)(p % 30);
            const float LF = 9.210340371976184f / 512.f;
            float pe;
            if (n & 1) pe = cosf(pos * expf(-(float)(n - 1) * LF));
            else       pe = sinf(pos * expf(-(float)n       * LF));
            g_E2[((size_t)r0 + q)*DD + n] = acc[q] + se_b[n] + style[b*DD + n] + pe;
        }
    }
}

// CW[d,j] = sum_k W1[d,k]*mm_w[k,j]; cb[d] = W1[d,:]·mm_b;  grid 512, block 64
__global__ void cw_kernel(const float* __restrict__ se_w, const float* __restrict__ mm_w,
                          const float* __restrict__ mm_b){
    int d = blockIdx.x, j = threadIdx.x;
    __shared__ float s_w1[DD];
    for (int k = j; k < DD; k += 64) s_w1[k] = se_w[(size_t)d*1024 + k];
    __syncthreads();
    float a = 0.f;
    for (int k = 0; k < DD; k++) a += s_w1[k] * mm_w[(size_t)k*MMM + j];
    g_CW[(size_t)d*MMM + j] = a;
    if (j == 0){
        float c = 0.f;
        for (int k = 0; k < DD; k++) c += s_w1[k] * mm_b[k];
        g_cb[d] = c;
    }
}

// x0 = (init_state@mm_w^T+mm_b)@W1^T + E2[b,0];  grid 8, block 512
__global__ void init_x0_kernel(const float* __restrict__ init_state, const float* __restrict__ mm_w,
                               const float* __restrict__ mm_b, const float* __restrict__ se_w){
    int b = blockIdx.x, d = threadIdx.x;
    __shared__ float s_feat[DD];
    float a = mm_b[d];
    const float* mw = mm_w + (size_t)d * MMM;
    const float* is = init_state + b * MMM;
#pragma unroll
    for (int k = 0; k < MMM; k++) a += is[k] * mw[k];
    s_feat[d] = a;
    __syncthreads();
    const float* w1 = se_w + (size_t)d * 1024;
    float a0=0.f,a1=0.f,a2=0.f,a3=0.f;
    for (int k = 0; k < DD; k += 4){
        a0 += s_feat[k]   * w1[k];
        a1 += s_feat[k+1] * w1[k+1];
        a2 += s_feat[k+2] * w1[k+2];
        a3 += s_feat[k+3] * w1[k+3];
    }
    g_xb[b*DD + d] = a0+a1+a2+a3 + g_E2[((size_t)b*FF + 0)*DD + d];
}

// ================= persistent decode kernel =================
__global__ void __launch_bounds__(256, 1) decode_kernel(
    const float* __restrict__ sa_in_w,  const float* __restrict__ sa_in_b,
    const float* __restrict__ sa_out_w, const float* __restrict__ sa_out_b,
    const float* __restrict__ ff1_w,    const float* __restrict__ ff1_b,
    const float* __restrict__ ff2_w,    const float* __restrict__ ff2_b,
    const float* __restrict__ ln_g,     const float* __restrict__ ln_b,
    const float* __restrict__ mmr_w,    const float* __restrict__ mmr_b,
    float* __restrict__ dec_out)
{
    int tid = threadIdx.x, w = tid >> 5, lane = tid & 31;
    int gw = blockIdx.x * 8 + w;
    __shared__ float s_x [BB][DD];     // 16 KB
    __shared__ float s_qb[8][DHH];     // 2 KB
    __shared__ float s_p [8][FF];      // 1.5 KB

    for (int t = 0; t < FF; t++){
        for (int l = 0; l < LLAY; l++){
            // ---- Stage A: layer input (LN3 fused for l>0) + qkv ----
            if (l == 0){
                for (int j = tid; j < BB*DD; j += 256) s_x[j >> 9][j & 511] = g_xb[j];
            } else {
                const float* lng = ln_g + ((size_t)(l-1)*3 + 2)*DD;
                const float* lnb = ln_b + ((size_t)(l-1)*3 + 2)*DD;
                int b = w;
                float v[16]; float s = 0.f;
#pragma unroll
                for (int q = 0; q < 16; q++){ int k = lane + q*32; float x = g_xa[b*DD+k] + g_y[b*DD+k]; v[q] = x; s += x; }
                s = warp_sum(s); float mu = s * (1.f/DD);
                float vs = 0.f;
#pragma unroll
                for (int q = 0; q < 16; q++){ float dv = v[q]-mu; vs += dv*dv; }
                vs = warp_sum(vs); float rstd = rsqrtf(vs*(1.f/DD) + LNEPS);
#pragma unroll
                for (int q = 0; q < 16; q++){ int k = lane + q*32; s_x[b][k] = (v[q]-mu)*rstd*lng[k] + lnb[k]; }
            }
            __syncthreads();
            if (l > 0 && blockIdx.x == 0){
                for (int j = tid; j < BB*DD; j += 256) g_xb[j] = s_x[j >> 9][j & 511];
            }
            {
                const float* Wqkv = sa_in_w + (size_t)l*3*DD*DD;
                const float* bqkv = sa_in_b + (size_t)l*3*DD;
                for (int rr = gw; rr < 3*DD; rr += NWARP){
                    const float* wr = Wqkv + (size_t)rr*DD;
                    float acc[8] = {0.f,0.f,0.f,0.f,0.f,0.f,0.f,0.f};
                    for (int k = lane; k < DD; k += 32){
                        float wv = wr[k];
#pragma unroll
                        for (int b = 0; b < 8; b++) acc[b] += wv * s_x[b][k];
                    }
#pragma unroll
                    for (int o = 16; o; o >>= 1){
#pragma unroll
                        for (int b = 0; b < 8; b++) acc[b] += __shfl_xor_sync(0xffffffffu, acc[b], o);
                    }
                    float bv = bqkv[rr];
#pragma unroll
                    for (int b = 0; b < 8; b++){
                        if (lane == b){
                            float val = acc[b] + bv;
                            if (rr < DD)        g_q[b*DD + rr] = val;
                            else if (rr < 2*DD) g_K[(((size_t)l*BB + b)*FF + t)*DD + (rr - DD)]   = val;
                            else                g_V[(((size_t)l*BB + b)*FF + t)*DD + (rr - 2*DD)] = val;
                        }
                    }
                }
            }
            grid_sync();

            // ---- B1: self-attention per (b,h) ----
            if (gw < BB*NHH){
                int b = gw >> 3, h = gw & 7;
                s_qb[w][lane]      = g_q[b*DD + h*DHH + lane];
                s_qb[w][lane + 32] = g_q[b*DD + h*DHH + lane + 32];
                __syncwarp();
                const float* Kb = g_K + (((size_t)l*BB + b)*FF)*DD + h*DHH;
                const float* Vb = g_V + (((size_t)l*BB + b)*FF)*DD + h*DHH;
                float slope = exp2f(-(float)(h + 1));
                int j0 = lane, j1 = lane + 32;
                float sc0 = -1e30f, sc1 = -1e30f;
                if (j0 <= t){
                    const float* kr = Kb + (size_t)j0*DD; float a = 0.f;
#pragma unroll
                    for (int d = 0; d < DHH; d++) a += s_qb[w][d]*kr[d];
                    sc0 = a*0.125f - slope * (float)((t - j0)/30);
                }
                if (j1 <= t){
                    const float* kr = Kb + (size_t)j1*DD; float a = 0.f;
#pragma unroll
                    for (int d = 0; d < DHH; d++) a += s_qb[w][d]*kr[d];
                    sc1 = a*0.125f - slope * (float)((t - j1)/30);
                }
                float m = fmaxf(sc0, sc1);
#pragma unroll
                for (int o = 16; o; o >>= 1) m = fmaxf(m, __shfl_xor_sync(0xffffffffu, m, o));
                float e0 = (j0 <= t) ? expf(sc0 - m) : 0.f;
                float e1 = (j1 <= t) ? expf(sc1 - m) : 0.f;
                float sm = warp_sum(e0 + e1);
                float inv = 1.f / sm;
                s_p[w][j0] = e0 * inv;
                if (j1 < FF) s_p[w][j1] = e1 * inv;
                __syncwarp();
#pragma unroll 2
                for (int dq = 0; dq < 2; dq++){
                    int d = lane + dq*32;
                    float a = 0.f;
                    for (int j = 0; j <= t; j++) a += s_p[w][j] * Vb[(size_t)j*DD + d];
                    g_attn[b*DD + h*DHH + d] = a;
                }
            }
            grid_sync();

            // ---- B2: out-proj + bias + residual ----
            {
                const float* Wo = sa_out_w + (size_t)l*DD*DD;
                const float* bo = sa_out_b + (size_t)l*DD;
                int u0 = gw * 4;                   // 4096 units over 1024 warps
                int b  = u0 >> 9;
                float av[16];
#pragma unroll
                for (int q = 0; q < 16; q++) av[q] = g_attn[b*DD + lane + q*32];
#pragma unroll
                for (int uq = 0; uq < 4; uq++){
                    int d = (u0 & 511) + uq;
                    const float* wr = Wo + (size_t)d*DD;
                    float a = 0.f;
#pragma unroll
                    for (int q = 0; q < 16; q++) a += av[q] * wr[lane + q*32];
                    a = warp_sum(a);
                    if (lane == 0) g_r[b*DD + d] = a + bo[d] + g_xb[b*DD + d];
                }
            }
            grid_sync();

            // ---- C: LN1 + XA + LN2 (redundant per block) then ff1 ----
            {
                const float* lng1 = ln_g + ((size_t)l*3 + 0)*DD;
                const float* lnb1 = ln_b + ((size_t)l*3 + 0)*DD;
                const float* lng2 = ln_g + ((size_t)l*3 + 1)*DD;
                const float* lnb2 = ln_b + ((size_t)l*3 + 1)*DD;
                int b = w;
                float v[16]; float s = 0.f;
#pragma unroll
                for (int q = 0; q < 16; q++){ int k = lane + q*32; float x = g_r[b*DD + k]; v[q] = x; s += x; }
                s = warp_sum(s); float mu = s * (1.f/DD);
                float vs = 0.f;
#pragma unroll
                for (int q = 0; q < 16; q++){ float dv = v[q]-mu; vs += dv*dv; }
                vs = warp_sum(vs); float rstd = rsqrtf(vs*(1.f/DD) + LNEPS);
                float s2 = 0.f;
#pragma unroll
                for (int q = 0; q < 16; q++){
                    int k = lane + q*32;
                    float x1 = (v[q]-mu)*rstd*lng1[k] + lnb1[k];
                    float r2 = x1 + g_XA[(((size_t)l*BB + b)*FF + t)*DD + k];
                    v[q] = r2; s2 += r2;
                }
                s2 = warp_sum(s2); mu = s2 * (1.f/DD);
                vs = 0.f;
#pragma unroll
                for (int q = 0; q < 16; q++){ float dv = v[q]-mu; vs += dv*dv; }
                vs = warp_sum(vs); rstd = rsqrtf(vs*(1.f/DD) + LNEPS);
#pragma unroll
                for (int q = 0; q < 16; q++){ int k = lane + q*32; s_x[b][k] = (v[q]-mu)*rstd*lng2[k] + lnb2[k]; }
            }
            __syncthreads();
            if (blockIdx.x == 0){
                for (int j = tid; j < BB*DD; j += 256) g_xa[j] = s_x[j >> 9][j & 511];
            }
            {
                const float* W1 = ff1_w + (size_t)l*DFFF*DD;
                const float* b1 = ff1_b + (size_t)l*DFFF;
                for (int rr = gw; rr < DFFF; rr += NWARP){
                    const float* wr = W1 + (size_t)rr*DD;
                    float acc[8] = {0.f,0.f,0.f,0.f,0.f,0.f,0.f,0.f};
                    for (int k = lane; k < DD; k += 32){
                        float wv = wr[k];
#pragma unroll
                        for (int b = 0; b < 8; b++) acc[b] += wv * s_x[b][k];
                    }
#pragma unroll
                    for (int o = 16; o; o >>= 1){
#pragma unroll
                        for (int b = 0; b < 8; b++) acc[b] += __shfl_xor_sync(0xffffffffu, acc[b], o);
                    }
                    float bv = b1[rr];
#pragma unroll
                    for (int b = 0; b < 8; b++)
                        if (lane == b) g_h[b*DFFF + rr] = fmaxf(acc[b] + bv, 0.f);
                }
            }
            grid_sync();

            // ---- D: ff2 ----
            if (gw < DD){
                const float* wr = ff2_w + (size_t)l*DD*DFFF + (size_t)gw*DFFF;
                float acc[8] = {0.f,0.f,0.f,0.f,0.f,0.f,0.f,0.f};
                for (int k = lane; k < DFFF; k += 32){
                    float wv = wr[k];
#pragma unroll
                    for (int b = 0; b < 8; b++) acc[b] += wv * g_h[b*DFFF + k];
                }
#pragma unroll
                for (int o = 16; o; o >>= 1){
#pragma unroll
                    for (int b = 0; b < 8; b++) acc[b] += __shfl_xor_sync(0xffffffffu, acc[b], o);
                }
                float bv = ff2_b[(size_t)l*DD + gw];
#pragma unroll
                for (int b = 0; b < 8; b++)
                    if (lane == b) g_y[b*DD + gw] = acc[b] + bv;
            }
            grid_sync();
        } // layers

        // ---- H1: LN3 + head projection ----
        if (gw < 512){
            int b = gw >> 6, j = gw & 63;
            const float* lng3 = ln_g + (size_t)(3*3 + 2)*DD;
            const float* lnb3 = ln_b + (size_t)(3*3 + 2)*DD;
            float v[16]; float s = 0.f;
#pragma unroll
            for (int q = 0; q < 16; q++){ int k = lane + q*32; float x = g_xa[b*DD+k] + g_y[b*DD+k]; v[q] = x; s += x; }
            s = warp_sum(s); float mu = s * (1.f/DD);
            float vs = 0.f;
#pragma unroll
            for (int q = 0; q < 16; q++){ float dv = v[q]-mu; vs += dv*dv; }
            vs = warp_sum(vs); float rstd = rsqrtf(vs*(1.f/DD) + LNEPS);
            float a = 0.f;
            const float* wr = mmr_w + (size_t)j*DD;
#pragma unroll
            for (int q = 0; q < 16; q++){
                int k = lane + q*32;
                float x3 = (v[q]-mu)*rstd*lng3[k] + lnb3[k];
                a += x3 * wr[k];
            }
            a = warp_sum(a);
            if (lane == 0){
                float val = a + mmr_b[j];
                dec_out[((size_t)b*FF + t)*MMM + j] = val;
                g_out[b*MMM + j] = val;
            }
        }
        grid_sync();

        // ---- H2: next embedding via folded CW (K=64) ----
        if (t < FF - 1){
            int u0 = gw * 4;
            int b  = u0 >> 9;
            float o0 = g_out[b*MMM + lane], o1 = g_out[b*MMM + lane + 32];
#pragma unroll
            for (int uq = 0; uq < 4; uq++){
                int d = (u0 & 511) + uq;
                const float* cw = g_CW + (size_t)d*MMM;
                float a = o0*cw[lane] + o1*cw[lane + 32];
                a = warp_sum(a);
                if (lane == 0)
                    g_xb[b*DD + d] = a + g_cb[d] + g_E2[((size_t)b*FF + t + 1)*DD + d];
            }
            grid_sync();
        }
    } // steps
}

// ---------------- launch ---------------------------------------------------------
extern "C" void kernel_launch(void* const* d_in, const int* in_sizes, int n_in,
                              void* d_out, int out_size){
    const float* content       = (const float*)d_in[0];
    const float* style_code    = (const float*)d_in[1];
    const float* style_hiddens = (const float*)d_in[2];
    const float* init_state    = (const float*)d_in[3];
    const float* ca_in_w  = (const float*)d_in[4];
    const float* ca_in_b  = (const float*)d_in[5];
    const float* ca_out_w = (const float*)d_in[6];
    const float* ca_out_b = (const float*)d_in[7];
    const float* se_w     = (const float*)d_in[8];
    const float* se_b     = (const float*)d_in[9];
    const float* mm_w     = (const float*)d_in[10];
    const float* mm_b     = (const float*)d_in[11];
    const float* mmr_w    = (const float*)d_in[12];
    const float* mmr_b    = (const float*)d_in[13];
    const float* sa_in_w  = (const float*)d_in[14];
    const float* sa_in_b  = (const float*)d_in[15];
    const float* sa_out_w = (const float*)d_in[16];
    const float* sa_out_b = (const float*)d_in[17];
    const float* xa_in_w  = (const float*)d_in[18];
    const float* xa_in_b  = (const float*)d_in[19];
    const float* xa_out_w = (const float*)d_in[20];
    const float* xa_out_b = (const float*)d_in[21];
    const float* ff1_w    = (const float*)d_in[22];
    const float* ff1_b    = (const float*)d_in[23];
    const float* ff2_w    = (const float*)d_in[24];
    const float* ff2_b    = (const float*)d_in[25];
    const float* ln_g     = (const float*)d_in[26];
    const float* ln_b     = (const float*)d_in[27];

    float* dec_out = (float*)d_out;                      // (B,48,64)
    float* sel     = (float*)d_out + BB*FF*MMM;          // (B,48,512)

    float *A_qh, *A_kh, *A_vh, *A_tmp, *A_XA;
    cudaGetSymbolAddress((void**)&A_qh,  g_qh);
    cudaGetSymbolAddress((void**)&A_kh,  g_kh);
    cudaGetSymbolAddress((void**)&A_vh,  g_vh);
    cudaGetSymbolAddress((void**)&A_tmp, g_tmp);
    cudaGetSymbolAddress((void**)&A_XA,  g_XA);

    dim3 blk(256);

    // ---- sel = CA(content, style_hiddens) (nh=1) ----
    gemm_rows_kernel<<<dim3(64,48), blk>>>(A_qh, content,       ca_in_w,           ca_in_b,        DD, DD);
    gemm_rows_kernel<<<dim3(64,64), blk>>>(A_kh, style_hiddens, ca_in_w +   DD*DD, ca_in_b +   DD, DD, DD);
    gemm_rows_kernel<<<dim3(64,64), blk>>>(A_vh, style_hiddens, ca_in_w + 2*DD*DD, ca_in_b + 2*DD, DD, DD);
    ca_attn_kernel<<<BB*FF, 256>>>(A_qh, A_kh, A_vh, A_tmp);
    gemm_rows_kernel<<<dim3(64,48), blk>>>(sel, A_tmp, ca_out_w, ca_out_b, DD, DD);

    // ---- XA[l] = (content @ Wv_l^T + bv_l) @ Wo_l^T + bo_l (diagonal-mask collapse) ----
    for (int l = 0; l < LLAY; l++){
        const float* wv = xa_in_w + (size_t)l*3*DD*DD + 2*DD*DD;
        const float* bv = xa_in_b + (size_t)l*3*DD    + 2*DD;
        gemm_rows_kernel<<<dim3(64,48), blk>>>(A_qh, content, wv, bv, DD, DD);
        gemm_rows_kernel<<<dim3(64,48), blk>>>(A_XA + (size_t)l*BB*FF*DD, A_qh,
                                               xa_out_w + (size_t)l*DD*DD,
                                               xa_out_b + (size_t)l*DD, DD, DD);
    }

    // ---- E2 table, folded head weights, x0 ----
    e2_kernel<<<dim3(64,48), 256>>>(sel, se_w, se_b, style_code);
    cw_kernel<<<DD, MMM>>>(se_w, mm_w, mm_b);
    init_x0_kernel<<<BB, 512>>>(init_state, mm_w, mm_b, se_w);

    // ---- persistent autoregressive decode (48 steps, grid-sync barriers) ----
    decode_kernel<<<GRID, 256>>>(sa_in_w, sa_in_b, sa_out_w, sa_out_b,
                                 ff1_w, ff1_b, ff2_w, ff2_b,
                                 ln_g, ln_b, mmr_w, mmr_b, dec_out);
}

// round 11
// speedup vs baseline: 3.0704x; 1.2710x over previous
#include <cuda_runtime.h>
#include <math.h>

#define BB   8
#define FF   48
#define SS   64
#define DD   512
#define NHH  8
#define DHH  64
#define LLAY 4
#define DFFF 2048
#define MMM  64
#define LNEPS 1e-5f
#define GRID 128          // persistent blocks (<= SM count -> all co-resident)
#define NWARP (GRID*8)    // 1024 warps

// ---------------- scratch (device globals; allocation-free) ----------------
__device__ float g_q   [BB*DD];
__device__ float g_xb  [BB*DD];           // layer input x (residual base)
__device__ float g_xa  [BB*DD];           // x2 after LN2
__device__ float g_y   [BB*DD];           // ff2 output
__device__ float g_h   [BB*DFFF];
__device__ float g_r   [BB*DD];           // out-proj + residual (pre-LN1)
__device__ float g_out [BB*MMM];
__device__ float g_K   [LLAY*BB*FF*DD];
__device__ float g_V   [LLAY*BB*FF*DD];
__device__ float g_XA  [LLAY*BB*FF*DD];   // precomputed cross-attn contribution
__device__ float g_E2  [BB*FF*DD];        // sel@W2 + se_b + style + PE
__device__ float g_CW  [DD*MMM];          // W1 @ mm_w  (512 x 64)
__device__ float g_cb  [DD];              // W1 @ mm_b
__device__ float g_qh  [BB*FF*DD];
__device__ float g_kh  [BB*SS*DD];
__device__ float g_vh  [BB*SS*DD];
__device__ float g_tmpL[LLAY*BB*FF*DD];

__device__ __align__(128) unsigned g_cnt1[32];   // barrier arrivals (own line)
__device__ __align__(128) unsigned g_gen1[32];   // barrier generation (own line)

// ---------------- helpers ----------------
__device__ __forceinline__ float warp_sum(float v){
#pragma unroll
    for (int o = 16; o; o >>= 1) v += __shfl_xor_sync(0xffffffffu, v, o);
    return v;
}

__device__ __forceinline__ void grid_sync(){
    __syncthreads();
    if (threadIdx.x == 0){
        unsigned g;
        asm volatile("ld.acquire.gpu.u32 %0, [%1];" : "=r"(g) : "l"(g_gen1) : "memory");
        unsigned prev;
        asm volatile("atom.add.acq_rel.gpu.u32 %0, [%1], 1;" : "=r"(prev) : "l"(g_cnt1) : "memory");
        if (prev == GRID - 1u){
            asm volatile("st.relaxed.gpu.u32 [%0], %1;" :: "l"(g_cnt1), "r"(0u) : "memory");
            asm volatile("st.release.gpu.u32 [%0], %1;" :: "l"(g_gen1), "r"(g + 1u) : "memory");
        } else {
            unsigned cur;
            do {
                asm volatile("ld.acquire.gpu.u32 %0, [%1];" : "=r"(cur) : "l"(g_gen1) : "memory");
            } while (cur == g);
        }
    }
    __syncthreads();
}

// ================= one-time precompute kernels =================

// out[r,n] = X[r,:]·W[n,:] + b[n];  grid=(N/8, R/8), block 256
__global__ void gemm_rows_kernel(float* __restrict__ out, const float* __restrict__ X,
                                 const float* __restrict__ W, const float* __restrict__ bias,
                                 int N, int K){
    int warp = threadIdx.x >> 5, lane = threadIdx.x & 31;
    int n  = blockIdx.x * 8 + warp;
    int r0 = blockIdx.y * 8;
    const float* w = W + (size_t)n * K;
    const float* x = X + (size_t)r0 * K;
    float acc[8] = {0.f,0.f,0.f,0.f,0.f,0.f,0.f,0.f};
    for (int k = lane; k < K; k += 32){
        float wv = w[k];
#pragma unroll
        for (int b = 0; b < 8; b++) acc[b] += wv * x[(size_t)b*K + k];
    }
#pragma unroll
    for (int o = 16; o; o >>= 1){
#pragma unroll
        for (int b = 0; b < 8; b++) acc[b] += __shfl_xor_sync(0xffffffffu, acc[b], o);
    }
    float bv = bias[n];
#pragma unroll
    for (int b = 0; b < 8; b++)
        if (lane == b) out[(size_t)(r0 + b) * N + n] = acc[b] + bv;
}

// z-gridded variant: grid=(N/8, Rmax/8, Z); strides select the z-th problem
__global__ void gemm_rows_z_kernel(float* __restrict__ out0, const float* __restrict__ X0,
                                   const float* __restrict__ W0, const float* __restrict__ b0,
                                   int N, int K, int R,
                                   size_t outSZ, size_t xSZ, size_t wSZ, size_t bSZ){
    int z = blockIdx.z;
    float* out = out0 + (size_t)z*outSZ;
    const float* X = X0 + (size_t)z*xSZ;
    const float* W = W0 + (size_t)z*wSZ;
    const float* bias = b0 + (size_t)z*bSZ;
    int warp = threadIdx.x >> 5, lane = threadIdx.x & 31;
    int n  = blockIdx.x * 8 + warp;
    int r0 = blockIdx.y * 8;
    if (r0 >= R) return;
    const float* w = W + (size_t)n * K;
    const float* x = X + (size_t)r0 * K;
    float acc[8] = {0.f,0.f,0.f,0.f,0.f,0.f,0.f,0.f};
    for (int k = lane; k < K; k += 32){
        float wv = w[k];
#pragma unroll
        for (int b = 0; b < 8; b++) acc[b] += wv * x[(size_t)b*K + k];
    }
#pragma unroll
    for (int o = 16; o; o >>= 1){
#pragma unroll
        for (int b = 0; b < 8; b++) acc[b] += __shfl_xor_sync(0xffffffffu, acc[b], o);
    }
    float bv = bias[n];
#pragma unroll
    for (int b = 0; b < 8; b++)
        if (lane == b) out[(size_t)(r0 + b) * N + n] = acc[b] + bv;
}

// CA in-proj: z=0 -> q(content, 384 rows), z=1 -> k(style, 512), z=2 -> v(style, 512)
__global__ void ca_inproj_kernel(const float* __restrict__ content, const float* __restrict__ style,
                                 const float* __restrict__ ca_in_w, const float* __restrict__ ca_in_b,
                                 float* __restrict__ qh, float* __restrict__ kh, float* __restrict__ vh){
    int z = blockIdx.z;
    const float* X = (z == 0) ? content : style;
    int R = (z == 0) ? BB*FF : BB*SS;
    float* out = (z == 0) ? qh : (z == 1 ? kh : vh);
    const float* W = ca_in_w + (size_t)z*DD*DD;
    const float* bias = ca_in_b + z*DD;
    int warp = threadIdx.x >> 5, lane = threadIdx.x & 31;
    int n  = blockIdx.x * 8 + warp;
    int r0 = blockIdx.y * 8;
    if (r0 >= R) return;
    const float* w = W + (size_t)n * DD;
    const float* x = X + (size_t)r0 * DD;
    float acc[8] = {0.f,0.f,0.f,0.f,0.f,0.f,0.f,0.f};
    for (int k = lane; k < DD; k += 32){
        float wv = w[k];
#pragma unroll
        for (int b = 0; b < 8; b++) acc[b] += wv * x[(size_t)b*DD + k];
    }
#pragma unroll
    for (int o = 16; o; o >>= 1){
#pragma unroll
        for (int b = 0; b < 8; b++) acc[b] += __shfl_xor_sync(0xffffffffu, acc[b], o);
    }
    float bv = bias[n];
#pragma unroll
    for (int b = 0; b < 8; b++)
        if (lane == b) out[(size_t)(r0 + b) * DD + n] = acc[b] + bv;
}

// sel cross-attn (nh=1, softmax over S=64); grid = B*F, block 256
__global__ void ca_attn_kernel(const float* __restrict__ qh, const float* __restrict__ kh,
                               const float* __restrict__ vh, float* __restrict__ o){
    int r = blockIdx.x;
    int b = r / FF;
    __shared__ float s_q[DD];
    __shared__ float s_p[SS];
    int tid = threadIdx.x, warp = tid >> 5, lane = tid & 31;
    for (int d = tid; d < DD; d += 256) s_q[d] = qh[(size_t)r*DD + d];
    __syncthreads();
    for (int s = warp; s < SS; s += 8){
        const float* kr = kh + (size_t)(b*SS + s)*DD;
        float a = 0.f;
        for (int k = lane; k < DD; k += 32) a += s_q[k] * kr[k];
        a = warp_sum(a);
        if (lane == 0) s_p[s] = a * 0.04419417382415922f;
    }
    __syncthreads();
    if (warp == 0){
        float v0 = s_p[lane], v1 = s_p[lane + 32];
        float m = fmaxf(v0, v1);
#pragma unroll
        for (int o2 = 16; o2; o2 >>= 1) m = fmaxf(m, __shfl_xor_sync(0xffffffffu, m, o2));
        float e0 = expf(v0 - m), e1 = expf(v1 - m);
        float sm = warp_sum(e0 + e1);
        float inv = 1.f / sm;
        s_p[lane] = e0 * inv; s_p[lane + 32] = e1 * inv;
    }
    __syncthreads();
    for (int d = tid; d < DD; d += 256){
        float a = 0.f;
#pragma unroll 8
        for (int s = 0; s < SS; s++) a += s_p[s] * vh[(size_t)(b*SS + s)*DD + d];
        o[(size_t)r*DD + d] = a;
    }
}

// E2[b,p,n] = sel[b,p?p-1:0]·W2[n,:] + se_b[n] + style[b,n] + PE[p,n]
__global__ void e2_kernel(const float* __restrict__ sel, const float* __restrict__ se_w,
                          const float* __restrict__ se_b, const float* __restrict__ style){
    int warp = threadIdx.x >> 5, lane = threadIdx.x & 31;
    int n  = blockIdx.x * 8 + warp;
    int r0 = blockIdx.y * 8;
    int b  = r0 / FF;
    const float* w = se_w + (size_t)n * 1024 + 512;
    const float* xr[8];
#pragma unroll
    for (int q = 0; q < 8; q++){
        int p  = (r0 + q) % FF;
        int ip = p ? (p - 1) : 0;
        xr[q] = sel + ((size_t)b*FF + ip)*DD;
    }
    float acc[8] = {0.f,0.f,0.f,0.f,0.f,0.f,0.f,0.f};
    for (int k = lane; k < DD; k += 32){
        float wv = w[k];
#pragma unroll
        for (int q = 0; q < 8; q++) acc[q] += wv * xr[q][k];
    }
#pragma unroll
    for (int o = 16; o; o >>= 1){
#pragma unroll
        for (int q = 0; q < 8; q++) acc[q] += __shfl_xor_sync(0xffffffffu, acc[q], o);
    }
#pragma unroll
    for (int q = 0; q < 8; q++){
        if (lane == q){
            int p = (r0 + q) % FF;
            float pos = (float)(p % 30);
            const float LF = 9.210340371976184f / 512.f;
            float pe;
            if (n & 1) pe = cosf(pos * expf(-(float)(n - 1) * LF));
            else       pe = sinf(pos * expf(-(float)n       * LF));
            g_E2[((size_t)r0 + q)*DD + n] = acc[q] + se_b[n] + style[b*DD + n] + pe;
        }
    }
}

// CW[d,j] = sum_k W1[d,k]*mm_w[k,j]; cb[d] = W1[d,:]·mm_b;  grid 512, block 64
__global__ void cw_kernel(const float* __restrict__ se_w, const float* __restrict__ mm_w,
                          const float* __restrict__ mm_b){
    int d = blockIdx.x, j = threadIdx.x;
    __shared__ float s_w1[DD];
    for (int k = j; k < DD; k += 64) s_w1[k] = se_w[(size_t)d*1024 + k];
    __syncthreads();
    float a = 0.f;
    for (int k = 0; k < DD; k++) a += s_w1[k] * mm_w[(size_t)k*MMM + j];
    g_CW[(size_t)d*MMM + j] = a;
    if (j == 0){
        float c = 0.f;
        for (int k = 0; k < DD; k++) c += s_w1[k] * mm_b[k];
        g_cb[d] = c;
    }
}

// x0 = (init_state@mm_w^T+mm_b)@W1^T + E2[b,0];  grid 8, block 512
__global__ void init_x0_kernel(const float* __restrict__ init_state, const float* __restrict__ mm_w,
                               const float* __restrict__ mm_b, const float* __restrict__ se_w){
    int b = blockIdx.x, d = threadIdx.x;
    __shared__ float s_feat[DD];
    float a = mm_b[d];
    const float* mw = mm_w + (size_t)d * MMM;
    const float* is = init_state + b * MMM;
#pragma unroll
    for (int k = 0; k < MMM; k++) a += is[k] * mw[k];
    s_feat[d] = a;
    __syncthreads();
    const float* w1 = se_w + (size_t)d * 1024;
    float a0=0.f,a1=0.f,a2=0.f,a3=0.f;
    for (int k = 0; k < DD; k += 4){
        a0 += s_feat[k]   * w1[k];
        a1 += s_feat[k+1] * w1[k+1];
        a2 += s_feat[k+2] * w1[k+2];
        a3 += s_feat[k+3] * w1[k+3];
    }
    g_xb[b*DD + d] = a0+a1+a2+a3 + g_E2[((size_t)b*FF + 0)*DD + d];
}

// ================= persistent decode kernel =================
__global__ void __launch_bounds__(256, 1) decode_kernel(
    const float* __restrict__ sa_in_w,  const float* __restrict__ sa_in_b,
    const float* __restrict__ sa_out_w, const float* __restrict__ sa_out_b,
    const float* __restrict__ ff1_w,    const float* __restrict__ ff1_b,
    const float* __restrict__ ff2_w,    const float* __restrict__ ff2_b,
    const float* __restrict__ ln_g,     const float* __restrict__ ln_b,
    const float* __restrict__ mmr_w,    const float* __restrict__ mmr_b,
    float* __restrict__ dec_out)
{
    int tid = threadIdx.x, w = tid >> 5, lane = tid & 31;
    int gw  = blockIdx.x * 8 + w;
    int myb = blockIdx.x >> 4;         // 16 blocks per batch
    int sub = blockIdx.x & 15;
    __shared__ float s_x [BB][DD];     // 16 KB
    __shared__ float s_attn[DD];       // 2 KB
    __shared__ float s_qb[8][DHH];     // 2 KB
    __shared__ float s_p [8][FF];      // 1.5 KB
    __shared__ float s_d [4][2][8];
    __shared__ float s_out[MMM];

    for (int t = 0; t < FF; t++){
        for (int l = 0; l < LLAY; l++){
            // ==== Stage A: layer input (LN3 of prev layer fused) + qkv ====
            if (l == 0){
                for (int j = tid; j < BB*DD; j += 256) s_x[j >> 9][j & 511] = g_xb[j];
            } else {
                const float* lng = ln_g + ((size_t)(l-1)*3 + 2)*DD;
                const float* lnb = ln_b + ((size_t)(l-1)*3 + 2)*DD;
                int b = w;
                float v[16]; float s = 0.f;
#pragma unroll
                for (int q = 0; q < 16; q++){ int k = lane + q*32; float x = g_xa[b*DD+k] + g_y[b*DD+k]; v[q] = x; s += x; }
                s = warp_sum(s); float mu = s * (1.f/DD);
                float vs = 0.f;
#pragma unroll
                for (int q = 0; q < 16; q++){ float dv = v[q]-mu; vs += dv*dv; }
                vs = warp_sum(vs); float rstd = rsqrtf(vs*(1.f/DD) + LNEPS);
#pragma unroll
                for (int q = 0; q < 16; q++){ int k = lane + q*32; s_x[b][k] = (v[q]-mu)*rstd*lng[k] + lnb[k]; }
            }
            __syncthreads();
            if (l > 0 && blockIdx.x == 0){
                for (int j = tid; j < BB*DD; j += 256) g_xb[j] = s_x[j >> 9][j & 511];
            }
            {
                const float* Wqkv = sa_in_w + (size_t)l*3*DD*DD;
                const float* bqkv = sa_in_b + (size_t)l*3*DD;
                for (int rr = gw; rr < 3*DD; rr += NWARP){
                    const float* wr = Wqkv + (size_t)rr*DD;
                    float acc[8] = {0.f,0.f,0.f,0.f,0.f,0.f,0.f,0.f};
                    for (int k = lane; k < DD; k += 32){
                        float wv = wr[k];
#pragma unroll
                        for (int b = 0; b < 8; b++) acc[b] += wv * s_x[b][k];
                    }
#pragma unroll
                    for (int o = 16; o; o >>= 1){
#pragma unroll
                        for (int b = 0; b < 8; b++) acc[b] += __shfl_xor_sync(0xffffffffu, acc[b], o);
                    }
                    float bv = bqkv[rr];
#pragma unroll
                    for (int b = 0; b < 8; b++){
                        if (lane == b){
                            float val = acc[b] + bv;
                            if (rr < DD)        g_q[b*DD + rr] = val;
                            else if (rr < 2*DD) g_K[(((size_t)l*BB + b)*FF + t)*DD + (rr - DD)]   = val;
                            else                g_V[(((size_t)l*BB + b)*FF + t)*DD + (rr - 2*DD)] = val;
                        }
                    }
                }
            }
            grid_sync();

            // ==== Stage B: attention (redundant per block, its batch) + out-proj ====
            {
                int b = myb, h = w;
                s_qb[w][lane]      = g_q[b*DD + h*DHH + lane];
                s_qb[w][lane + 32] = g_q[b*DD + h*DHH + lane + 32];
                __syncwarp();
                const float* Kb = g_K + (((size_t)l*BB + b)*FF)*DD + h*DHH;
                const float* Vb = g_V + (((size_t)l*BB + b)*FF)*DD + h*DHH;
                float slope = exp2f(-(float)(h + 1));
                int j0 = lane, j1 = lane + 32;
                float sc0 = -1e30f, sc1 = -1e30f;
                if (j0 <= t){
                    const float* kr = Kb + (size_t)j0*DD; float a = 0.f;
#pragma unroll
                    for (int d = 0; d < DHH; d++) a += s_qb[w][d]*kr[d];
                    sc0 = a*0.125f - slope * (float)((t - j0)/30);
                }
                if (j1 <= t){
                    const float* kr = Kb + (size_t)j1*DD; float a = 0.f;
#pragma unroll
                    for (int d = 0; d < DHH; d++) a += s_qb[w][d]*kr[d];
                    sc1 = a*0.125f - slope * (float)((t - j1)/30);
                }
                float m = fmaxf(sc0, sc1);
#pragma unroll
                for (int o = 16; o; o >>= 1) m = fmaxf(m, __shfl_xor_sync(0xffffffffu, m, o));
                float e0 = (j0 <= t) ? expf(sc0 - m) : 0.f;
                float e1 = (j1 <= t) ? expf(sc1 - m) : 0.f;
                float sm = warp_sum(e0 + e1);
                float inv = 1.f / sm;
                s_p[w][j0] = e0 * inv;
                if (j1 < FF) s_p[w][j1] = e1 * inv;
                __syncwarp();
#pragma unroll 2
                for (int dq = 0; dq < 2; dq++){
                    int d = lane + dq*32;
                    float a = 0.f;
                    for (int j = 0; j <= t; j++) a += s_p[w][j] * Vb[(size_t)j*DD + d];
                    s_attn[h*DHH + d] = a;
                }
            }
            __syncthreads();
            {
                const float* Wo = sa_out_w + (size_t)l*DD*DD;
                const float* bo = sa_out_b + (size_t)l*DD;
                float av[16];
#pragma unroll
                for (int q = 0; q < 16; q++) av[q] = s_attn[lane + q*32];
#pragma unroll
                for (int uq = 0; uq < 4; uq++){
                    int d = sub*32 + w*4 + uq;
                    const float* wr = Wo + (size_t)d*DD;
                    float a = 0.f;
#pragma unroll
                    for (int q = 0; q < 16; q++) a += av[q] * wr[lane + q*32];
                    a = warp_sum(a);
                    if (lane == 0) g_r[myb*DD + d] = a + bo[d] + g_xb[myb*DD + d];
                }
            }
            grid_sync();

            // ==== Stage C: LN1 + XA + LN2 (redundant per block) then ff1 ====
            {
                const float* lng1 = ln_g + ((size_t)l*3 + 0)*DD;
                const float* lnb1 = ln_b + ((size_t)l*3 + 0)*DD;
                const float* lng2 = ln_g + ((size_t)l*3 + 1)*DD;
                const float* lnb2 = ln_b + ((size_t)l*3 + 1)*DD;
                int b = w;
                float v[16]; float s = 0.f;
#pragma unroll
                for (int q = 0; q < 16; q++){ int k = lane + q*32; float x = g_r[b*DD + k]; v[q] = x; s += x; }
                s = warp_sum(s); float mu = s * (1.f/DD);
                float vs = 0.f;
#pragma unroll
                for (int q = 0; q < 16; q++){ float dv = v[q]-mu; vs += dv*dv; }
                vs = warp_sum(vs); float rstd = rsqrtf(vs*(1.f/DD) + LNEPS);
                float s2 = 0.f;
#pragma unroll
                for (int q = 0; q < 16; q++){
                    int k = lane + q*32;
                    float x1 = (v[q]-mu)*rstd*lng1[k] + lnb1[k];
                    float r2 = x1 + g_XA[(((size_t)l*BB + b)*FF + t)*DD + k];
                    v[q] = r2; s2 += r2;
                }
                s2 = warp_sum(s2); mu = s2 * (1.f/DD);
                vs = 0.f;
#pragma unroll
                for (int q = 0; q < 16; q++){ float dv = v[q]-mu; vs += dv*dv; }
                vs = warp_sum(vs); rstd = rsqrtf(vs*(1.f/DD) + LNEPS);
#pragma unroll
                for (int q = 0; q < 16; q++){ int k = lane + q*32; s_x[b][k] = (v[q]-mu)*rstd*lng2[k] + lnb2[k]; }
            }
            __syncthreads();
            if (blockIdx.x == 0){
                for (int j = tid; j < BB*DD; j += 256) g_xa[j] = s_x[j >> 9][j & 511];
            }
            {
                const float* W1 = ff1_w + (size_t)l*DFFF*DD;
                const float* b1 = ff1_b + (size_t)l*DFFF;
                for (int rr = gw; rr < DFFF; rr += NWARP){
                    const float* wr = W1 + (size_t)rr*DD;
                    float acc[8] = {0.f,0.f,0.f,0.f,0.f,0.f,0.f,0.f};
                    for (int k = lane; k < DD; k += 32){
                        float wv = wr[k];
#pragma unroll
                        for (int b = 0; b < 8; b++) acc[b] += wv * s_x[b][k];
                    }
#pragma unroll
                    for (int o = 16; o; o >>= 1){
#pragma unroll
                        for (int b = 0; b < 8; b++) acc[b] += __shfl_xor_sync(0xffffffffu, acc[b], o);
                    }
                    float bv = b1[rr];
#pragma unroll
                    for (int b = 0; b < 8; b++)
                        if (lane == b) g_h[b*DFFF + rr] = fmaxf(acc[b] + bv, 0.f);
                }
            }
            grid_sync();

            // ==== Stage D: ff2 (split-K: 2 warps per output row) ====
            {
                int rloc = w >> 1, half = w & 1;
                int rr = blockIdx.x * 4 + rloc;            // 0..511
                const float* wr = ff2_w + (size_t)l*DD*DFFF + (size_t)rr*DFFF + half*1024;
                const float* hh = g_h + half*1024;
                float acc[8] = {0.f,0.f,0.f,0.f,0.f,0.f,0.f,0.f};
                for (int k = lane; k < 1024; k += 32){
                    float wv = wr[k];
#pragma unroll
                    for (int b = 0; b < 8; b++) acc[b] += wv * hh[(size_t)b*DFFF + k];
                }
#pragma unroll
                for (int o = 16; o; o >>= 1){
#pragma unroll
                    for (int b = 0; b < 8; b++) acc[b] += __shfl_xor_sync(0xffffffffu, acc[b], o);
                }
                if (lane < 8) s_d[rloc][half][lane] = acc[lane];
                __syncthreads();
                if (w < 4 && lane < 8){
                    int r2 = blockIdx.x * 4 + w;
                    g_y[lane*DD + r2] = s_d[w][0][lane] + s_d[w][1][lane] + ff2_b[(size_t)l*DD + r2];
                }
            }
            grid_sync();
        } // layers

        // ==== Stage H: LN3 + head (redundant per block, its batch) + next emb ====
        {
            int b = myb;
            const float* lng3 = ln_g + (size_t)((LLAY-1)*3 + 2)*DD;
            const float* lnb3 = ln_b + (size_t)((LLAY-1)*3 + 2)*DD;
            float x3[16]; float s = 0.f;
#pragma unroll
            for (int q = 0; q < 16; q++){ int k = lane + q*32; float x = g_xa[b*DD+k] + g_y[b*DD+k]; x3[q] = x; s += x; }
            s = warp_sum(s); float mu = s * (1.f/DD);
            float vs = 0.f;
#pragma unroll
            for (int q = 0; q < 16; q++){ float dv = x3[q]-mu; vs += dv*dv; }
            vs = warp_sum(vs); float rstd = rsqrtf(vs*(1.f/DD) + LNEPS);
#pragma unroll
            for (int q = 0; q < 16; q++){ int k = lane + q*32; x3[q] = (x3[q]-mu)*rstd*lng3[k] + lnb3[k]; }
#pragma unroll
            for (int jj = 0; jj < 8; jj++){
                int j = w*8 + jj;
                const float* wr = mmr_w + (size_t)j*DD;
                float a = 0.f;
#pragma unroll
                for (int q = 0; q < 16; q++) a += x3[q] * wr[lane + q*32];
                a = warp_sum(a);
                if (lane == 0){
                    float val = a + mmr_b[j];
                    s_out[j] = val;
                    dec_out[((size_t)b*FF + t)*MMM + j] = val;   // redundant same-value writes OK
                }
            }
            __syncthreads();
            if (t < FF - 1){
                float o0 = s_out[lane], o1 = s_out[lane + 32];
#pragma unroll
                for (int uq = 0; uq < 4; uq++){
                    int d = sub*32 + w*4 + uq;
                    const float* cw = g_CW + (size_t)d*MMM;
                    float a = o0*cw[lane] + o1*cw[lane + 32];
                    a = warp_sum(a);
                    if (lane == 0)
                        g_xb[b*DD + d] = a + g_cb[d] + g_E2[((size_t)b*FF + t + 1)*DD + d];
                }
            }
        }
        if (t < FF - 1) grid_sync();
    } // steps
}

// ---------------- launch ---------------------------------------------------------
extern "C" void kernel_launch(void* const* d_in, const int* in_sizes, int n_in,
                              void* d_out, int out_size){
    const float* content       = (const float*)d_in[0];
    const float* style_code    = (const float*)d_in[1];
    const float* style_hiddens = (const float*)d_in[2];
    const float* init_state    = (const float*)d_in[3];
    const float* ca_in_w  = (const float*)d_in[4];
    const float* ca_in_b  = (const float*)d_in[5];
    const float* ca_out_w = (const float*)d_in[6];
    const float* ca_out_b = (const float*)d_in[7];
    const float* se_w     = (const float*)d_in[8];
    const float* se_b     = (const float*)d_in[9];
    const float* mm_w     = (const float*)d_in[10];
    const float* mm_b     = (const float*)d_in[11];
    const float* mmr_w    = (const float*)d_in[12];
    const float* mmr_b    = (const float*)d_in[13];
    const float* sa_in_w  = (const float*)d_in[14];
    const float* sa_in_b  = (const float*)d_in[15];
    const float* sa_out_w = (const float*)d_in[16];
    const float* sa_out_b = (const float*)d_in[17];
    const float* xa_in_w  = (const float*)d_in[18];
    const float* xa_in_b  = (const float*)d_in[19];
    const float* xa_out_w = (const float*)d_in[20];
    const float* xa_out_b = (const float*)d_in[21];
    const float* ff1_w    = (const float*)d_in[22];
    const float* ff1_b    = (const float*)d_in[23];
    const float* ff2_w    = (const float*)d_in[24];
    const float* ff2_b    = (const float*)d_in[25];
    const float* ln_g     = (const float*)d_in[26];
    const float* ln_b     = (const float*)d_in[27];

    float* dec_out = (float*)d_out;                      // (B,48,64)
    float* sel     = (float*)d_out + BB*FF*MMM;          // (B,48,512)

    float *A_qh, *A_kh, *A_vh, *A_tmpL, *A_XA;
    cudaGetSymbolAddress((void**)&A_qh,   g_qh);
    cudaGetSymbolAddress((void**)&A_kh,   g_kh);
    cudaGetSymbolAddress((void**)&A_vh,   g_vh);
    cudaGetSymbolAddress((void**)&A_tmpL, g_tmpL);
    cudaGetSymbolAddress((void**)&A_XA,   g_XA);

    dim3 blk(256);

    // ---- sel = CA(content, style_hiddens) (nh=1): 3 launches total ----
    // grid.y = 64 covers 512 rows (k/v); z=0 (q, 384 rows) trimmed by in-kernel guard
    ca_inproj_kernel<<<dim3(64, 64, 3), blk>>>(content, style_hiddens, ca_in_w, ca_in_b,
                                               A_qh, A_kh, A_vh);
    ca_attn_kernel<<<BB*FF, 256>>>(A_qh, A_kh, A_vh, A_tmpL);
    gemm_rows_kernel<<<dim3(64, 48), blk>>>(sel, A_tmpL, ca_out_w, ca_out_b, DD, DD);

    // ---- XA[l] = (content @ Wv_l^T + bv_l) @ Wo_l^T + bo_l: 2 z-gridded launches ----
    gemm_rows_z_kernel<<<dim3(64, 48, LLAY), blk>>>(
        A_tmpL, content, xa_in_w + 2*DD*DD, xa_in_b + 2*DD,
        DD, DD, BB*FF,
        (size_t)BB*FF*DD, 0, (size_t)3*DD*DD, (size_t)3*DD);
    gemm_rows_z_kernel<<<dim3(64, 48, LLAY), blk>>>(
        A_XA, A_tmpL, xa_out_w, xa_out_b,
        DD, DD, BB*FF,
        (size_t)BB*FF*DD, (size_t)BB*FF*DD, (size_t)DD*DD, (size_t)DD);

    // ---- E2 table, folded head weights, x0 ----
    e2_kernel<<<dim3(64, 48), 256>>>(sel, se_w, se_b, style_code);
    cw_kernel<<<DD, MMM>>>(se_w, mm_w, mm_b);
    init_x0_kernel<<<BB, 512>>>(init_state, mm_w, mm_b, se_w);

    // ---- persistent autoregressive decode (48 steps, grid-sync barriers) ----
    decode_kernel<<<GRID, 256>>>(sa_in_w, sa_in_b, sa_out_w, sa_out_b,
                                 ff1_w, ff1_b, ff2_w, ff2_b,
                                 ln_g, ln_b, mmr_w, mmr_b, dec_out);
}

// round 12
// speedup vs baseline: 4.1192x; 1.3416x over previous
#include <cuda_runtime.h>
#include <math.h>

#define BB   8
#define FF   48
#define SS   64
#define DD   512
#define NHH  8
#define DHH  64
#define LLAY 4
#define DFFF 2048
#define MMM  64
#define LNEPS 1e-5f
#define GRID 128          // persistent blocks (<= SM count -> all co-resident)
#define NWARP (GRID*8)    // 1024 warps

// ---------------- scratch (device globals; allocation-free) ----------------
__device__ __align__(16) float g_q   [BB*DD];
__device__ __align__(16) float g_xb  [BB*DD];
__device__ __align__(16) float g_xa  [BB*DD];
__device__ __align__(16) float g_y   [BB*DD];
__device__ __align__(16) float g_h   [BB*DFFF];
__device__ __align__(16) float g_r   [BB*DD];
__device__ __align__(16) float g_K   [LLAY*BB*FF*DD];
__device__ __align__(16) float g_V   [LLAY*BB*FF*DD];
__device__ __align__(16) float g_XA  [LLAY*BB*FF*DD];
__device__ __align__(16) float g_E2  [BB*FF*DD];
__device__ __align__(16) float g_CW  [DD*MMM];
__device__ __align__(16) float g_cb  [DD];
__device__ __align__(16) float g_qh  [BB*FF*DD];
__device__ __align__(16) float g_kh  [BB*SS*DD];
__device__ __align__(16) float g_vh  [BB*SS*DD];
__device__ __align__(16) float g_tmpL[LLAY*BB*FF*DD];

// tree barrier state: 8 group counters (own lines) + root + generation
__device__ __align__(128) unsigned g_gcnt[8*32];
__device__ __align__(128) unsigned g_root[32];
__device__ __align__(128) unsigned g_gen1[32];

// ---------------- helpers ----------------
__device__ __forceinline__ float warp_sum(float v){
#pragma unroll
    for (int o = 16; o; o >>= 1) v += __shfl_xor_sync(0xffffffffu, v, o);
    return v;
}

__device__ __forceinline__ float dot4(float4 a, float4 b){
    return a.x*b.x + a.y*b.y + a.z*b.z + a.w*b.w;
}

// two-level tree barrier; monotonic counters, phase tracked per-thread
__device__ __forceinline__ void grid_sync(unsigned &phase, int grp){
    __syncthreads();
    if (threadIdx.x == 0){
        unsigned p;
        asm volatile("atom.add.acq_rel.gpu.u32 %0, [%1], 1;"
                     : "=r"(p) : "l"(&g_gcnt[grp*32]) : "memory");
        if (p == phase*16u + 15u){
            unsigned q;
            asm volatile("atom.add.acq_rel.gpu.u32 %0, [%1], 1;"
                         : "=r"(q) : "l"(g_root) : "memory");
            if (q == phase*8u + 7u){
                asm volatile("st.release.gpu.u32 [%0], %1;"
                             :: "l"(g_gen1), "r"(phase + 1u) : "memory");
            }
        }
        unsigned cur;
        do {
            asm volatile("ld.acquire.gpu.u32 %0, [%1];" : "=r"(cur) : "l"(g_gen1) : "memory");
        } while (cur <= phase);
    }
    phase++;
    __syncthreads();
}

__global__ void reset_barrier_kernel(){
    int t = threadIdx.x;
    if (t < 8) g_gcnt[t*32] = 0;
    if (t == 8) g_root[0] = 0;
    if (t == 9) g_gen1[0] = 0;
}

// ================= one-time precompute kernels =================

// out[r,n] = X[r,:]·W[n,:] + b[n];  grid=(N/8, R/8), block 256, K multiple of 128
__global__ void gemm_rows_kernel(float* __restrict__ out, const float* __restrict__ X,
                                 const float* __restrict__ W, const float* __restrict__ bias,
                                 int N, int K){
    int warp = threadIdx.x >> 5, lane = threadIdx.x & 31;
    int n  = blockIdx.x * 8 + warp;
    int r0 = blockIdx.y * 8;
    const float4* w4 = (const float4*)(W + (size_t)n * K);
    const float* x = X + (size_t)r0 * K;
    int K4 = K >> 2;
    float acc[8] = {0.f,0.f,0.f,0.f,0.f,0.f,0.f,0.f};
    for (int i = lane; i < K4; i += 32){
        float4 wv = w4[i];
#pragma unroll
        for (int b = 0; b < 8; b++)
            acc[b] += dot4(wv, ((const float4*)(x + (size_t)b*K))[i]);
    }
#pragma unroll
    for (int o = 16; o; o >>= 1){
#pragma unroll
        for (int b = 0; b < 8; b++) acc[b] += __shfl_xor_sync(0xffffffffu, acc[b], o);
    }
    float bv = bias[n];
#pragma unroll
    for (int b = 0; b < 8; b++)
        if (lane == b) out[(size_t)(r0 + b) * N + n] = acc[b] + bv;
}

// z-gridded variant
__global__ void gemm_rows_z_kernel(float* __restrict__ out0, const float* __restrict__ X0,
                                   const float* __restrict__ W0, const float* __restrict__ b0,
                                   int N, int K, int R,
                                   size_t outSZ, size_t xSZ, size_t wSZ, size_t bSZ){
    int z = blockIdx.z;
    float* out = out0 + (size_t)z*outSZ;
    const float* X = X0 + (size_t)z*xSZ;
    const float* W = W0 + (size_t)z*wSZ;
    const float* bias = b0 + (size_t)z*bSZ;
    int warp = threadIdx.x >> 5, lane = threadIdx.x & 31;
    int n  = blockIdx.x * 8 + warp;
    int r0 = blockIdx.y * 8;
    if (r0 >= R) return;
    const float4* w4 = (const float4*)(W + (size_t)n * K);
    const float* x = X + (size_t)r0 * K;
    int K4 = K >> 2;
    float acc[8] = {0.f,0.f,0.f,0.f,0.f,0.f,0.f,0.f};
    for (int i = lane; i < K4; i += 32){
        float4 wv = w4[i];
#pragma unroll
        for (int b = 0; b < 8; b++)
            acc[b] += dot4(wv, ((const float4*)(x + (size_t)b*K))[i]);
    }
#pragma unroll
    for (int o = 16; o; o >>= 1){
#pragma unroll
        for (int b = 0; b < 8; b++) acc[b] += __shfl_xor_sync(0xffffffffu, acc[b], o);
    }
    float bv = bias[n];
#pragma unroll
    for (int b = 0; b < 8; b++)
        if (lane == b) out[(size_t)(r0 + b) * N + n] = acc[b] + bv;
}

// CA in-proj: z=0 -> q(content, 384 rows), z=1 -> k(style, 512), z=2 -> v(style, 512)
__global__ void ca_inproj_kernel(const float* __restrict__ content, const float* __restrict__ style,
                                 const float* __restrict__ ca_in_w, const float* __restrict__ ca_in_b,
                                 float* __restrict__ qh, float* __restrict__ kh, float* __restrict__ vh){
    int z = blockIdx.z;
    const float* X = (z == 0) ? content : style;
    int R = (z == 0) ? BB*FF : BB*SS;
    float* out = (z == 0) ? qh : (z == 1 ? kh : vh);
    const float* W = ca_in_w + (size_t)z*DD*DD;
    const float* bias = ca_in_b + z*DD;
    int warp = threadIdx.x >> 5, lane = threadIdx.x & 31;
    int n  = blockIdx.x * 8 + warp;
    int r0 = blockIdx.y * 8;
    if (r0 >= R) return;
    const float4* w4 = (const float4*)(W + (size_t)n * DD);
    const float* x = X + (size_t)r0 * DD;
    float acc[8] = {0.f,0.f,0.f,0.f,0.f,0.f,0.f,0.f};
#pragma unroll
    for (int q = 0; q < 4; q++){
        int i = lane + q*32;
        float4 wv = w4[i];
#pragma unroll
        for (int b = 0; b < 8; b++)
            acc[b] += dot4(wv, ((const float4*)(x + (size_t)b*DD))[i]);
    }
#pragma unroll
    for (int o = 16; o; o >>= 1){
#pragma unroll
        for (int b = 0; b < 8; b++) acc[b] += __shfl_xor_sync(0xffffffffu, acc[b], o);
    }
    float bv = bias[n];
#pragma unroll
    for (int b = 0; b < 8; b++)
        if (lane == b) out[(size_t)(r0 + b) * DD + n] = acc[b] + bv;
}

// sel cross-attn (nh=1, softmax over S=64); grid = B*F, block 256
__global__ void ca_attn_kernel(const float* __restrict__ qh, const float* __restrict__ kh,
                               const float* __restrict__ vh, float* __restrict__ o){
    int r = blockIdx.x;
    int b = r / FF;
    __shared__ __align__(16) float s_q[DD];
    __shared__ float s_p[SS];
    int tid = threadIdx.x, warp = tid >> 5, lane = tid & 31;
    for (int d = tid; d < DD; d += 256) s_q[d] = qh[(size_t)r*DD + d];
    __syncthreads();
    for (int s = warp; s < SS; s += 8){
        const float4* kr4 = (const float4*)(kh + (size_t)(b*SS + s)*DD);
        float a = 0.f;
#pragma unroll
        for (int q = 0; q < 4; q++){
            int i = lane + q*32;
            a += dot4(((const float4*)s_q)[i], kr4[i]);
        }
        a = warp_sum(a);
        if (lane == 0) s_p[s] = a * 0.04419417382415922f;
    }
    __syncthreads();
    if (warp == 0){
        float v0 = s_p[lane], v1 = s_p[lane + 32];
        float m = fmaxf(v0, v1);
#pragma unroll
        for (int o2 = 16; o2; o2 >>= 1) m = fmaxf(m, __shfl_xor_sync(0xffffffffu, m, o2));
        float e0 = expf(v0 - m), e1 = expf(v1 - m);
        float sm = warp_sum(e0 + e1);
        float inv = 1.f / sm;
        s_p[lane] = e0 * inv; s_p[lane + 32] = e1 * inv;
    }
    __syncthreads();
    for (int d = tid; d < DD; d += 256){
        float a = 0.f;
#pragma unroll 8
        for (int s = 0; s < SS; s++) a += s_p[s] * vh[(size_t)(b*SS + s)*DD + d];
        o[(size_t)r*DD + d] = a;
    }
}

// E2[b,p,n] = sel[b,p?p-1:0]·W2[n,:] + se_b[n] + style[b,n] + PE[p,n]
__global__ void e2_kernel(const float* __restrict__ sel, const float* __restrict__ se_w,
                          const float* __restrict__ se_b, const float* __restrict__ style){
    int warp = threadIdx.x >> 5, lane = threadIdx.x & 31;
    int n  = blockIdx.x * 8 + warp;
    int r0 = blockIdx.y * 8;
    int b  = r0 / FF;
    const float4* w4 = (const float4*)(se_w + (size_t)n * 1024 + 512);
    const float4* xr[8];
#pragma unroll
    for (int q = 0; q < 8; q++){
        int p  = (r0 + q) % FF;
        int ip = p ? (p - 1) : 0;
        xr[q] = (const float4*)(sel + ((size_t)b*FF + ip)*DD);
    }
    float acc[8] = {0.f,0.f,0.f,0.f,0.f,0.f,0.f,0.f};
#pragma unroll
    for (int i4 = 0; i4 < 4; i4++){
        int i = lane + i4*32;
        float4 wv = w4[i];
#pragma unroll
        for (int q = 0; q < 8; q++) acc[q] += dot4(wv, xr[q][i]);
    }
#pragma unroll
    for (int o = 16; o; o >>= 1){
#pragma unroll
        for (int q = 0; q < 8; q++) acc[q] += __shfl_xor_sync(0xffffffffu, acc[q], o);
    }
#pragma unroll
    for (int q = 0; q < 8; q++){
        if (lane == q){
            int p = (r0 + q) % FF;
            float pos = (float)(p % 30);
            const float LF = 9.210340371976184f / 512.f;
            float pe;
            if (n & 1) pe = cosf(pos * expf(-(float)(n - 1) * LF));
            else       pe = sinf(pos * expf(-(float)n       * LF));
            g_E2[((size_t)r0 + q)*DD + n] = acc[q] + se_b[n] + style[b*DD + n] + pe;
        }
    }
}

// CW[d,j] = sum_k W1[d,k]*mm_w[k,j]; cb[d] = W1[d,:]·mm_b;  grid 512, block 64
__global__ void cw_kernel(const float* __restrict__ se_w, const float* __restrict__ mm_w,
                          const float* __restrict__ mm_b){
    int d = blockIdx.x, j = threadIdx.x;
    __shared__ float s_w1[DD];
    for (int k = j; k < DD; k += 64) s_w1[k] = se_w[(size_t)d*1024 + k];
    __syncthreads();
    float a = 0.f;
    for (int k = 0; k < DD; k++) a += s_w1[k] * mm_w[(size_t)k*MMM + j];
    g_CW[(size_t)d*MMM + j] = a;
    if (j == 0){
        float c = 0.f;
        for (int k = 0; k < DD; k++) c += s_w1[k] * mm_b[k];
        g_cb[d] = c;
    }
}

// x0 = (init_state@mm_w^T+mm_b)@W1^T + E2[b,0];  grid 8, block 512
__global__ void init_x0_kernel(const float* __restrict__ init_state, const float* __restrict__ mm_w,
                               const float* __restrict__ mm_b, const float* __restrict__ se_w){
    int b = blockIdx.x, d = threadIdx.x;
    __shared__ __align__(16) float s_feat[DD];
    float a = mm_b[d];
    const float* mw = mm_w + (size_t)d * MMM;
    const float* is = init_state + b * MMM;
#pragma unroll
    for (int k = 0; k < MMM; k++) a += is[k] * mw[k];
    s_feat[d] = a;
    __syncthreads();
    const float4* w14 = (const float4*)(se_w + (size_t)d * 1024);
    float acc = 0.f;
#pragma unroll
    for (int i = 0; i < 128; i++) acc += dot4(((const float4*)s_feat)[i], w14[i]);
    g_xb[b*DD + d] = acc + g_E2[((size_t)b*FF + 0)*DD + d];
}

// ================= persistent decode kernel =================
__global__ void __launch_bounds__(256, 1) decode_kernel(
    const float* __restrict__ sa_in_w,  const float* __restrict__ sa_in_b,
    const float* __restrict__ sa_out_w, const float* __restrict__ sa_out_b,
    const float* __restrict__ ff1_w,    const float* __restrict__ ff1_b,
    const float* __restrict__ ff2_w,    const float* __restrict__ ff2_b,
    const float* __restrict__ ln_g,     const float* __restrict__ ln_b,
    const float* __restrict__ mmr_w,    const float* __restrict__ mmr_b,
    float* __restrict__ dec_out)
{
    int tid = threadIdx.x, w = tid >> 5, lane = tid & 31;
    int gw  = blockIdx.x * 8 + w;
    int myb = blockIdx.x >> 4;         // 16 blocks per batch
    int sub = blockIdx.x & 15;
    int grp = blockIdx.x >> 4;         // barrier group (16 blocks)
    unsigned phase = 0;
    __shared__ __align__(16) float s_x [BB][DD];
    __shared__ __align__(16) float s_attn[DD];
    __shared__ __align__(16) float s_qb[8][DHH];
    __shared__ float s_p [8][FF];
    __shared__ float s_d [4][2][8];
    __shared__ float s_out[MMM];

    for (int t = 0; t < FF; t++){
        for (int l = 0; l < LLAY; l++){
            // ==== Stage A: layer input (LN3 of prev layer fused) + qkv ====
            if (l == 0){
#pragma unroll
                for (int j = tid; j < BB*DD/4; j += 256)
                    ((float4*)s_x)[j] = ((const float4*)g_xb)[j];
            } else {
                const float4* lng = (const float4*)(ln_g + ((size_t)(l-1)*3 + 2)*DD);
                const float4* lnb = (const float4*)(ln_b + ((size_t)(l-1)*3 + 2)*DD);
                int b = w;
                float4 v[4]; float s = 0.f;
#pragma unroll
                for (int q = 0; q < 4; q++){
                    int i = lane + q*32;
                    float4 xa = ((const float4*)(g_xa + b*DD))[i];
                    float4 yy = ((const float4*)(g_y  + b*DD))[i];
                    v[q].x = xa.x+yy.x; v[q].y = xa.y+yy.y; v[q].z = xa.z+yy.z; v[q].w = xa.w+yy.w;
                    s += v[q].x+v[q].y+v[q].z+v[q].w;
                }
                s = warp_sum(s); float mu = s * (1.f/DD);
                float vs = 0.f;
#pragma unroll
                for (int q = 0; q < 4; q++){
                    float dx=v[q].x-mu, dy=v[q].y-mu, dz=v[q].z-mu, dw=v[q].w-mu;
                    vs += dx*dx+dy*dy+dz*dz+dw*dw;
                }
                vs = warp_sum(vs); float rstd = rsqrtf(vs*(1.f/DD) + LNEPS);
#pragma unroll
                for (int q = 0; q < 4; q++){
                    int i = lane + q*32;
                    float4 g = lng[i], bb = lnb[i], o;
                    o.x = (v[q].x-mu)*rstd*g.x + bb.x;
                    o.y = (v[q].y-mu)*rstd*g.y + bb.y;
                    o.z = (v[q].z-mu)*rstd*g.z + bb.z;
                    o.w = (v[q].w-mu)*rstd*g.w + bb.w;
                    ((float4*)s_x[b])[i] = o;
                }
            }
            __syncthreads();
            if (l > 0 && blockIdx.x == 0){
#pragma unroll
                for (int j = tid; j < BB*DD/4; j += 256)
                    ((float4*)g_xb)[j] = ((const float4*)s_x)[j];
            }
            {
                const float* Wqkv = sa_in_w + (size_t)l*3*DD*DD;
                const float* bqkv = sa_in_b + (size_t)l*3*DD;
                for (int rr = gw; rr < 3*DD; rr += NWARP){
                    const float4* wr4 = (const float4*)(Wqkv + (size_t)rr*DD);
                    float acc[8] = {0.f,0.f,0.f,0.f,0.f,0.f,0.f,0.f};
#pragma unroll
                    for (int q = 0; q < 4; q++){
                        int i = lane + q*32;
                        float4 wv = wr4[i];
#pragma unroll
                        for (int b = 0; b < 8; b++)
                            acc[b] += dot4(wv, ((const float4*)s_x[b])[i]);
                    }
#pragma unroll
                    for (int o = 16; o; o >>= 1){
#pragma unroll
                        for (int b = 0; b < 8; b++) acc[b] += __shfl_xor_sync(0xffffffffu, acc[b], o);
                    }
                    float bv = bqkv[rr];
#pragma unroll
                    for (int b = 0; b < 8; b++){
                        if (lane == b){
                            float val = acc[b] + bv;
                            if (rr < DD)        g_q[b*DD + rr] = val;
                            else if (rr < 2*DD) g_K[(((size_t)l*BB + b)*FF + t)*DD + (rr - DD)]   = val;
                            else                g_V[(((size_t)l*BB + b)*FF + t)*DD + (rr - 2*DD)] = val;
                        }
                    }
                }
            }
            grid_sync(phase, grp);

            // ==== Stage B: attention (redundant per block, its batch) + out-proj ====
            {
                int b = myb, h = w;
                s_qb[w][lane]      = g_q[b*DD + h*DHH + lane];
                s_qb[w][lane + 32] = g_q[b*DD + h*DHH + lane + 32];
                __syncwarp();
                const float* Kb = g_K + (((size_t)l*BB + b)*FF)*DD + h*DHH;
                const float* Vb = g_V + (((size_t)l*BB + b)*FF)*DD + h*DHH;
                float slope = exp2f(-(float)(h + 1));
                int j0 = lane, j1 = lane + 32;
                float sc0 = -1e30f, sc1 = -1e30f;
                if (j0 <= t){
                    const float4* kr4 = (const float4*)(Kb + (size_t)j0*DD);
                    float a = 0.f;
#pragma unroll
                    for (int i = 0; i < 16; i++) a += dot4(((const float4*)s_qb[w])[i], kr4[i]);
                    sc0 = a*0.125f - slope * (float)((t - j0)/30);
                }
                if (j1 <= t){
                    const float4* kr4 = (const float4*)(Kb + (size_t)j1*DD);
                    float a = 0.f;
#pragma unroll
                    for (int i = 0; i < 16; i++) a += dot4(((const float4*)s_qb[w])[i], kr4[i]);
                    sc1 = a*0.125f - slope * (float)((t - j1)/30);
                }
                float m = fmaxf(sc0, sc1);
#pragma unroll
                for (int o = 16; o; o >>= 1) m = fmaxf(m, __shfl_xor_sync(0xffffffffu, m, o));
                float e0 = (j0 <= t) ? expf(sc0 - m) : 0.f;
                float e1 = (j1 <= t) ? expf(sc1 - m) : 0.f;
                float sm = warp_sum(e0 + e1);
                float inv = 1.f / sm;
                s_p[w][j0] = e0 * inv;
                if (j1 < FF) s_p[w][j1] = e1 * inv;
                __syncwarp();
#pragma unroll 2
                for (int dq = 0; dq < 2; dq++){
                    int d = lane + dq*32;
                    float a = 0.f;
                    for (int j = 0; j <= t; j++) a += s_p[w][j] * Vb[(size_t)j*DD + d];
                    s_attn[h*DHH + d] = a;
                }
            }
            __syncthreads();
            {
                const float* Wo = sa_out_w + (size_t)l*DD*DD;
                const float* bo = sa_out_b + (size_t)l*DD;
                float4 av[4];
#pragma unroll
                for (int q = 0; q < 4; q++) av[q] = ((const float4*)s_attn)[lane + q*32];
#pragma unroll
                for (int uq = 0; uq < 4; uq++){
                    int d = sub*32 + w*4 + uq;
                    const float4* wr4 = (const float4*)(Wo + (size_t)d*DD);
                    float a = 0.f;
#pragma unroll
                    for (int q = 0; q < 4; q++) a += dot4(av[q], wr4[lane + q*32]);
                    a = warp_sum(a);
                    if (lane == 0) g_r[myb*DD + d] = a + bo[d] + g_xb[myb*DD + d];
                }
            }
            grid_sync(phase, grp);

            // ==== Stage C: LN1 + XA + LN2 (redundant per block) then ff1 ====
            {
                const float4* lng1 = (const float4*)(ln_g + ((size_t)l*3 + 0)*DD);
                const float4* lnb1 = (const float4*)(ln_b + ((size_t)l*3 + 0)*DD);
                const float4* lng2 = (const float4*)(ln_g + ((size_t)l*3 + 1)*DD);
                const float4* lnb2 = (const float4*)(ln_b + ((size_t)l*3 + 1)*DD);
                int b = w;
                const float4* xa4 = (const float4*)(g_XA + (((size_t)l*BB + b)*FF + t)*DD);
                float4 v[4]; float s = 0.f;
#pragma unroll
                for (int q = 0; q < 4; q++){
                    v[q] = ((const float4*)(g_r + b*DD))[lane + q*32];
                    s += v[q].x+v[q].y+v[q].z+v[q].w;
                }
                s = warp_sum(s); float mu = s * (1.f/DD);
                float vs = 0.f;
#pragma unroll
                for (int q = 0; q < 4; q++){
                    float dx=v[q].x-mu, dy=v[q].y-mu, dz=v[q].z-mu, dw=v[q].w-mu;
                    vs += dx*dx+dy*dy+dz*dz+dw*dw;
                }
                vs = warp_sum(vs); float rstd = rsqrtf(vs*(1.f/DD) + LNEPS);
                float s2 = 0.f;
#pragma unroll
                for (int q = 0; q < 4; q++){
                    int i = lane + q*32;
                    float4 g = lng1[i], bb = lnb1[i], xa = xa4[i], r2;
                    r2.x = (v[q].x-mu)*rstd*g.x + bb.x + xa.x;
                    r2.y = (v[q].y-mu)*rstd*g.y + bb.y + xa.y;
                    r2.z = (v[q].z-mu)*rstd*g.z + bb.z + xa.z;
                    r2.w = (v[q].w-mu)*rstd*g.w + bb.w + xa.w;
                    v[q] = r2; s2 += r2.x+r2.y+r2.z+r2.w;
                }
                s2 = warp_sum(s2); mu = s2 * (1.f/DD);
                vs = 0.f;
#pragma unroll
                for (int q = 0; q < 4; q++){
                    float dx=v[q].x-mu, dy=v[q].y-mu, dz=v[q].z-mu, dw=v[q].w-mu;
                    vs += dx*dx+dy*dy+dz*dz+dw*dw;
                }
                vs = warp_sum(vs); rstd = rsqrtf(vs*(1.f/DD) + LNEPS);
#pragma unroll
                for (int q = 0; q < 4; q++){
                    int i = lane + q*32;
                    float4 g = lng2[i], bb = lnb2[i], o;
                    o.x = (v[q].x-mu)*rstd*g.x + bb.x;
                    o.y = (v[q].y-mu)*rstd*g.y + bb.y;
                    o.z = (v[q].z-mu)*rstd*g.z + bb.z;
                    o.w = (v[q].w-mu)*rstd*g.w + bb.w;
                    ((float4*)s_x[b])[i] = o;
                }
            }
            __syncthreads();
            if (blockIdx.x == 0){
#pragma unroll
                for (int j = tid; j < BB*DD/4; j += 256)
                    ((float4*)g_xa)[j] = ((const float4*)s_x)[j];
            }
            {
                const float* W1 = ff1_w + (size_t)l*DFFF*DD;
                const float* b1 = ff1_b + (size_t)l*DFFF;
                for (int rr = gw; rr < DFFF; rr += NWARP){
                    const float4* wr4 = (const float4*)(W1 + (size_t)rr*DD);
                    float acc[8] = {0.f,0.f,0.f,0.f,0.f,0.f,0.f,0.f};
#pragma unroll
                    for (int q = 0; q < 4; q++){
                        int i = lane + q*32;
                        float4 wv = wr4[i];
#pragma unroll
                        for (int b = 0; b < 8; b++)
                            acc[b] += dot4(wv, ((const float4*)s_x[b])[i]);
                    }
#pragma unroll
                    for (int o = 16; o; o >>= 1){
#pragma unroll
                        for (int b = 0; b < 8; b++) acc[b] += __shfl_xor_sync(0xffffffffu, acc[b], o);
                    }
                    float bv = b1[rr];
#pragma unroll
                    for (int b = 0; b < 8; b++)
                        if (lane == b) g_h[b*DFFF + rr] = fmaxf(acc[b] + bv, 0.f);
                }
            }
            grid_sync(phase, grp);

            // ==== Stage D: ff2 (split-K: 2 warps per output row) ====
            {
                int rloc = w >> 1, half = w & 1;
                int rr = blockIdx.x * 4 + rloc;            // 0..511
                const float4* wr4 = (const float4*)(ff2_w + (size_t)l*DD*DFFF + (size_t)rr*DFFF + half*1024);
                const float* hh = g_h + half*1024;
                float acc[8] = {0.f,0.f,0.f,0.f,0.f,0.f,0.f,0.f};
#pragma unroll
                for (int q = 0; q < 8; q++){
                    int i = lane + q*32;
                    float4 wv = wr4[i];
#pragma unroll
                    for (int b = 0; b < 8; b++)
                        acc[b] += dot4(wv, ((const float4*)(hh + (size_t)b*DFFF))[i]);
                }
#pragma unroll
                for (int o = 16; o; o >>= 1){
#pragma unroll
                    for (int b = 0; b < 8; b++) acc[b] += __shfl_xor_sync(0xffffffffu, acc[b], o);
                }
                if (lane < 8) s_d[rloc][half][lane] = acc[lane];
                __syncthreads();
                if (w < 4 && lane < 8){
                    int r2 = blockIdx.x * 4 + w;
                    g_y[lane*DD + r2] = s_d[w][0][lane] + s_d[w][1][lane] + ff2_b[(size_t)l*DD + r2];
                }
            }
            grid_sync(phase, grp);
        } // layers

        // ==== Stage H: LN3 + head (redundant per block, its batch) + next emb ====
        {
            int b = myb;
            const float4* lng3 = (const float4*)(ln_g + (size_t)((LLAY-1)*3 + 2)*DD);
            const float4* lnb3 = (const float4*)(ln_b + (size_t)((LLAY-1)*3 + 2)*DD);
            float4 x3[4]; float s = 0.f;
#pragma unroll
            for (int q = 0; q < 4; q++){
                int i = lane + q*32;
                float4 xa = ((const float4*)(g_xa + b*DD))[i];
                float4 yy = ((const float4*)(g_y  + b*DD))[i];
                x3[q].x = xa.x+yy.x; x3[q].y = xa.y+yy.y; x3[q].z = xa.z+yy.z; x3[q].w = xa.w+yy.w;
                s += x3[q].x+x3[q].y+x3[q].z+x3[q].w;
            }
            s = warp_sum(s); float mu = s * (1.f/DD);
            float vs = 0.f;
#pragma unroll
            for (int q = 0; q < 4; q++){
                float dx=x3[q].x-mu, dy=x3[q].y-mu, dz=x3[q].z-mu, dw=x3[q].w-mu;
                vs += dx*dx+dy*dy+dz*dz+dw*dw;
            }
            vs = warp_sum(vs); float rstd = rsqrtf(vs*(1.f/DD) + LNEPS);
#pragma unroll
            for (int q = 0; q < 4; q++){
                int i = lane + q*32;
                float4 g = lng3[i], bb = lnb3[i];
                x3[q].x = (x3[q].x-mu)*rstd*g.x + bb.x;
                x3[q].y = (x3[q].y-mu)*rstd*g.y + bb.y;
                x3[q].z = (x3[q].z-mu)*rstd*g.z + bb.z;
                x3[q].w = (x3[q].w-mu)*rstd*g.w + bb.w;
            }
#pragma unroll
            for (int jj = 0; jj < 8; jj++){
                int j = w*8 + jj;
                const float4* wr4 = (const float4*)(mmr_w + (size_t)j*DD);
                float a = 0.f;
#pragma unroll
                for (int q = 0; q < 4; q++) a += dot4(x3[q], wr4[lane + q*32]);
                a = warp_sum(a);
                if (lane == 0){
                    float val = a + mmr_b[j];
                    s_out[j] = val;
                    dec_out[((size_t)b*FF + t)*MMM + j] = val;
                }
            }
            __syncthreads();
            if (t < FF - 1){
                float o0 = s_out[lane], o1 = s_out[lane + 32];
#pragma unroll
                for (int uq = 0; uq < 4; uq++){
                    int d = sub*32 + w*4 + uq;
                    const float* cw = g_CW + (size_t)d*MMM;
                    float a = o0*cw[lane] + o1*cw[lane + 32];
                    a = warp_sum(a);
                    if (lane == 0)
                        g_xb[b*DD + d] = a + g_cb[d] + g_E2[((size_t)b*FF + t + 1)*DD + d];
                }
            }
        }
        if (t < FF - 1) grid_sync(phase, grp);
    } // steps
}

// ---------------- launch ---------------------------------------------------------
extern "C" void kernel_launch(void* const* d_in, const int* in_sizes, int n_in,
                              void* d_out, int out_size){
    const float* content       = (const float*)d_in[0];
    const float* style_code    = (const float*)d_in[1];
    const float* style_hiddens = (const float*)d_in[2];
    const float* init_state    = (const float*)d_in[3];
    const float* ca_in_w  = (const float*)d_in[4];
    const float* ca_in_b  = (const float*)d_in[5];
    const float* ca_out_w = (const float*)d_in[6];
    const float* ca_out_b = (const float*)d_in[7];
    const float* se_w     = (const float*)d_in[8];
    const float* se_b     = (const float*)d_in[9];
    const float* mm_w     = (const float*)d_in[10];
    const float* mm_b     = (const float*)d_in[11];
    const float* mmr_w    = (const float*)d_in[12];
    const float* mmr_b    = (const float*)d_in[13];
    const float* sa_in_w  = (const float*)d_in[14];
    const float* sa_in_b  = (const float*)d_in[15];
    const float* sa_out_w = (const float*)d_in[16];
    const float* sa_out_b = (const float*)d_in[17];
    const float* xa_in_w  = (const float*)d_in[18];
    const float* xa_in_b  = (const float*)d_in[19];
    const float* xa_out_w = (const float*)d_in[20];
    const float* xa_out_b = (const float*)d_in[21];
    const float* ff1_w    = (const float*)d_in[22];
    const float* ff1_b    = (const float*)d_in[23];
    const float* ff2_w    = (const float*)d_in[24];
    const float* ff2_b    = (const float*)d_in[25];
    const float* ln_g     = (const float*)d_in[26];
    const float* ln_b     = (const float*)d_in[27];

    float* dec_out = (float*)d_out;                      // (B,48,64)
    float* sel     = (float*)d_out + BB*FF*MMM;          // (B,48,512)

    float *A_qh, *A_kh, *A_vh, *A_tmpL, *A_XA;
    cudaGetSymbolAddress((void**)&A_qh,   g_qh);
    cudaGetSymbolAddress((void**)&A_kh,   g_kh);
    cudaGetSymbolAddress((void**)&A_vh,   g_vh);
    cudaGetSymbolAddress((void**)&A_tmpL, g_tmpL);
    cudaGetSymbolAddress((void**)&A_XA,   g_XA);

    dim3 blk(256);

    // ---- sel = CA(content, style_hiddens) (nh=1) ----
    ca_inproj_kernel<<<dim3(64, 64, 3), blk>>>(content, style_hiddens, ca_in_w, ca_in_b,
                                               A_qh, A_kh, A_vh);
    ca_attn_kernel<<<BB*FF, 256>>>(A_qh, A_kh, A_vh, A_tmpL);
    gemm_rows_kernel<<<dim3(64, 48), blk>>>(sel, A_tmpL, ca_out_w, ca_out_b, DD, DD);

    // ---- XA[l] = (content @ Wv_l^T + bv_l) @ Wo_l^T + bo_l ----
    gemm_rows_z_kernel<<<dim3(64, 48, LLAY), blk>>>(
        A_tmpL, content, xa_in_w + 2*DD*DD, xa_in_b + 2*DD,
        DD, DD, BB*FF,
        (size_t)BB*FF*DD, 0, (size_t)3*DD*DD, (size_t)3*DD);
    gemm_rows_z_kernel<<<dim3(64, 48, LLAY), blk>>>(
        A_XA, A_tmpL, xa_out_w, xa_out_b,
        DD, DD, BB*FF,
        (size_t)BB*FF*DD, (size_t)BB*FF*DD, (size_t)DD*DD, (size_t)DD);

    // ---- E2 table, folded head weights, x0, barrier reset ----
    e2_kernel<<<dim3(64, 48), 256>>>(sel, se_w, se_b, style_code);
    cw_kernel<<<DD, MMM>>>(se_w, mm_w, mm_b);
    init_x0_kernel<<<BB, 512>>>(init_state, mm_w, mm_b, se_w);
    reset_barrier_kernel<<<1, 32>>>();

    // ---- persistent autoregressive decode (48 steps, tree-barrier grid sync) ----
    decode_kernel<<<GRID, 256>>>(sa_in_w, sa_in_b, sa_out_w, sa_out_b,
                                 ff1_w, ff1_b, ff2_w, ff2_b,
                                 ln_g, ln_b, mmr_w, mmr_b, dec_out);
}